// round 10
// baseline (speedup 1.0000x reference)
#include <cuda_runtime.h>
#include <math.h>

// ---------------- problem constants ----------------
#define Nb    32
#define Pfr   75
#define NGRID 3
#define NFRAG 9
#define CROPS 64
#define PUZ   225
#define IMGS  224
#define PATCH 16
#define NPT   196
#define Dm    768
#define NHEAD 12
#define HD    64
#define NL    12
#define MLPD  3072
#define NCLS  1000
#define TOKS  197
#define ROWS  (Nb*TOKS)   // 6304

// ---------------- scratch (static device globals; no allocation) ----------------
__device__ float g_img[Nb*3*PUZ*PUZ];
__device__ float g_patches[(size_t)Nb*NPT*Dm];
__device__ float g_ptok[(size_t)Nb*NPT*Dm];
__device__ float g_tok[(size_t)ROWS*Dm];
__device__ float g_h[(size_t)ROWS*Dm];
__device__ float g_qkv[(size_t)ROWS*3*Dm];
__device__ float g_atto[(size_t)ROWS*Dm];
__device__ float g_mlp[(size_t)ROWS*MLPD];
__device__ float g_cls[Nb*Dm];
__device__ float g_feat[Nb*NCLS];
__device__ float g_fc1[Nb*NCLS];
__device__ int   g_shuffle[Nb*NFRAG];
__device__ int   g_offs[Nb*NFRAG*2];
__device__ int   g_jitt[Nb*NFRAG*3];

// ---------------- threefry2x32 (KAT-verified core) ----------------
__device__ __forceinline__ void threefry(unsigned k0, unsigned k1, unsigned &x0, unsigned &x1) {
    unsigned ks0 = k0, ks1 = k1, ks2 = k0 ^ k1 ^ 0x1BD11BDAu;
    x0 += ks0; x1 += ks1;
#define TFRND(r) { x0 += x1; x1 = (x1 << (r)) | (x1 >> (32 - (r))); x1 ^= x0; }
    TFRND(13) TFRND(15) TFRND(26) TFRND(6);  x0 += ks1; x1 += ks2 + 1u;
    TFRND(17) TFRND(29) TFRND(16) TFRND(24); x0 += ks2; x1 += ks0 + 2u;
    TFRND(13) TFRND(15) TFRND(26) TFRND(6);  x0 += ks0; x1 += ks1 + 3u;
    TFRND(17) TFRND(29) TFRND(16) TFRND(24); x0 += ks1; x1 += ks2 + 4u;
    TFRND(13) TFRND(15) TFRND(26) TFRND(6);  x0 += ks2; x1 += ks0 + 5u;
#undef TFRND
}

// modern partitionable 32-bit random bits: element i -> xor-fold of threefry(key, (0, i))
__device__ __forceinline__ unsigned rb32_part(unsigned k0, unsigned k1, unsigned i) {
    unsigned x0 = 0u, x1 = i;
    threefry(k0, k1, x0, x1);
    return x0 ^ x1;
}

// modern foldlike split: subkey t of split(key) = threefry(key, (0, t))
__device__ __forceinline__ void split_key(unsigned k0, unsigned k1, unsigned t,
                                          unsigned &o0, unsigned &o1) {
    unsigned x0 = 0u, x1 = t;
    threefry(k0, k1, x0, x1);
    o0 = x0; o1 = x1;
}

// ---------------- kernel 1: RNG setup + target output (modern x32 + split-randint) ----------------
// keys layout in shared: [kn0,kn1, kc0,kc1, kj0,kj1, kc1a,kc1b, kc2a,kc2b, kj1a,kj1b, kj2a,kj2b]
__global__ void rng_kernel(float* target_out) {
    __shared__ unsigned keys[14];
    __shared__ float noise[Nb*NFRAG];
    int tid = threadIdx.x;

    if (tid == 0) {
        // split key(42) into 3 subkeys
        for (int t = 0; t < 3; t++)
            split_key(0u, 42u, (unsigned)t, keys[2*t], keys[2*t+1]);
        // randint internal splits: k_crop -> (kc1, kc2), k_jit -> (kj1, kj2)
        split_key(keys[2], keys[3], 0u, keys[6],  keys[7]);
        split_key(keys[2], keys[3], 1u, keys[8],  keys[9]);
        split_key(keys[4], keys[5], 0u, keys[10], keys[11]);
        split_key(keys[4], keys[5], 1u, keys[12], keys[13]);
    }
    __syncthreads();

    // noise: uniform(k_noise, (32,9)) -- xor-fold per element
    if (tid < Nb*NFRAG) {
        unsigned bits = rb32_part(keys[0], keys[1], (unsigned)tid);
        noise[tid] = __uint_as_float((bits >> 9) | 0x3F800000u) - 1.0f;
    }
    __syncthreads();

    // per-batch stable argsort of 9 values -> shuffle + restore + target
    if (tid < Nb) {
        int ids[NFRAG];
        unsigned used = 0;
        for (int r = 0; r < NFRAG; r++) {
            int best = -1;
            for (int j = 0; j < NFRAG; j++) {
                if (used & (1u << j)) continue;
                if (best < 0 || noise[tid*NFRAG + j] < noise[tid*NFRAG + best]) best = j;
            }
            ids[r] = best; used |= (1u << best);
        }
        int rest[NFRAG];
        for (int r = 0; r < NFRAG; r++) { g_shuffle[tid*NFRAG + r] = ids[r]; rest[ids[r]] = r; }
        if (target_out) {
            for (int f = 0; f < NFRAG; f++) {
                target_out[(tid*NFRAG + f)*2 + 0] = (float)(rest[f] / 3);
                target_out[(tid*NFRAG + f)*2 + 1] = (float)(rest[f] % 3);
            }
        }
    }

    // offs: randint(k_crop, (288,2), 0, 12)
    // JAX: k1,k2 = split(k_crop); hi = bits(k1, shape); lo = bits(k2, shape)
    // span=12: multiplier = ((2^16 % 12)^2) % 12 = 4
    for (int i = tid; i < Nb*NFRAG*2; i += blockDim.x) {
        unsigned hi = rb32_part(keys[6], keys[7], (unsigned)i);
        unsigned lo = rb32_part(keys[8], keys[9], (unsigned)i);
        unsigned v = (((hi % 12u) * 4u) + (lo % 12u)) % 12u;
        g_offs[i] = (int)v;
    }
    // jit: randint(k_jit, (288,3,1,1), -2, 3); span=5, multiplier = 1
    for (int i = tid; i < Nb*NFRAG*3; i += blockDim.x) {
        unsigned hi = rb32_part(keys[10], keys[11], (unsigned)i);
        unsigned lo = rb32_part(keys[12], keys[13], (unsigned)i);
        unsigned v = ((hi % 5u) + (lo % 5u)) % 5u;
        g_jitt[i] = (int)v - 2;
    }
}

// ---------------- block reductions (blockDim == 256) ----------------
__device__ __forceinline__ float bsum256(float v, float* red8) {
    for (int o = 16; o; o >>= 1) v += __shfl_xor_sync(0xFFFFFFFFu, v, o);
    if ((threadIdx.x & 31) == 0) red8[threadIdx.x >> 5] = v;
    __syncthreads();
    float r = red8[0]+red8[1]+red8[2]+red8[3]+red8[4]+red8[5]+red8[6]+red8[7];
    __syncthreads();
    return r;
}

// ---------------- kernel 2: augment ----------------
__global__ void augment_kernel(const float* __restrict__ x) {
    __shared__ float buf[Pfr*Pfr];
    __shared__ float red8[8];
    int bfc = blockIdx.x;
    int c = bfc % 3;
    int bf = bfc / 3;
    int b = bf / NFRAG, f = bf % NFRAG;

    int src = g_shuffle[bf];
    int sr = (src / 3) * Pfr + g_offs[2*bf + 0];
    int sc = (src % 3) * Pfr + g_offs[2*bf + 1];
    float jitv = (float)g_jitt[bf*3 + c];
    const float* xp = x + ((size_t)b*3 + c) * PUZ * PUZ;

    const float sf = 64.0f / 75.0f;
    float lsum = 0.f;
    for (int idx = threadIdx.x; idx < Pfr*Pfr; idx += 256) {
        int i = idx / Pfr, j = idx % Pfr;
        float fy = (i + 0.5f) * sf - 0.5f;
        float fx = (j + 0.5f) * sf - 0.5f;
        int   y0 = (int)floorf(fy); float dy = fy - (float)y0;
        int   x0 = (int)floorf(fx); float dx = fx - (float)x0;
        int y0c = max(0, min(63, y0)),   y1c = max(0, min(63, y0 + 1));
        int x0c = max(0, min(63, x0)),   x1c = max(0, min(63, x0 + 1));
        const float* r0 = xp + (size_t)(sr + y0c) * PUZ + sc;
        const float* r1 = xp + (size_t)(sr + y1c) * PUZ + sc;
        float v = (1.f-dy)*((1.f-dx)*r0[x0c] + dx*r0[x1c])
                +       dy*((1.f-dx)*r1[x0c] + dx*r1[x1c]);
        v = v + jitv;
        v = fminf(fmaxf(v, 0.f), 255.f);
        buf[idx] = v;
        lsum += v;
    }
    float m = bsum256(lsum, red8) * (1.0f / (Pfr*Pfr));
    float lss = 0.f;
    for (int idx = threadIdx.x; idx < Pfr*Pfr; idx += 256) {
        float d = buf[idx] - m;
        lss += d * d;
    }
    float ss = bsum256(lss, red8);
    float s = sqrtf(ss / (float)(Pfr*Pfr - 1));
    if (s == 0.f) s = 1.f;

    int gi = f / 3, gj = f % 3;
    float* op = g_img + ((size_t)b*3 + c) * PUZ * PUZ + (size_t)gi*Pfr*PUZ + gj*Pfr;
    for (int idx = threadIdx.x; idx < Pfr*Pfr; idx += 256) {
        op[(idx / Pfr) * PUZ + (idx % Pfr)] = (buf[idx] - m) / s;
    }
}

// ---------------- kernel 3: patchify ----------------
__global__ void patchify_kernel() {
    int idx = blockIdx.x * blockDim.x + threadIdx.x;
    if (idx >= Nb*NPT*Dm) return;
    int k = idx % Dm;
    int p = (idx / Dm) % NPT;
    int b = idx / (Dm * NPT);
    int c = k >> 8, u = (k >> 4) & 15, v = k & 15;
    int pi = p / 14, pj = p % 14;
    g_patches[idx] = g_img[(((size_t)b*3 + c) * PUZ + (pi*16 + u)) * PUZ + (pj*16 + v)];
}

// ---------------- kernel 4: token assemble ----------------
__global__ void assemble_kernel(const float* __restrict__ clstok, const float* __restrict__ pos) {
    int idx = blockIdx.x * blockDim.x + threadIdx.x;
    if (idx >= Nb*TOKS*Dm) return;
    int d = idx % Dm;
    int t = (idx / Dm) % TOKS;
    int b = idx / (Dm * TOKS);
    float v = (t == 0) ? clstok[d] : g_ptok[((size_t)b*NPT + (t-1))*Dm + d];
    g_tok[idx] = v + pos[t*Dm + d];
}

// ---------------- kernel 5: layernorm ----------------
__global__ void ln_kernel(const float* __restrict__ x, long long sx,
                          const float* __restrict__ s, const float* __restrict__ b,
                          float* __restrict__ y, long long sy) {
    __shared__ float red8[8];
    const float* xr = x + (long long)blockIdx.x * sx;
    float* yr = y + (long long)blockIdx.x * sy;
    int t = threadIdx.x;
    float v0 = xr[t], v1 = xr[t+256], v2 = xr[t+512];
    float m = bsum256(v0+v1+v2, red8) * (1.0f/768.0f);
    float d0 = v0-m, d1 = v1-m, d2 = v2-m;
    float var = bsum256(d0*d0 + d1*d1 + d2*d2, red8) * (1.0f/768.0f);
    float inv = rsqrtf(var + 1e-6f);
    yr[t]     = d0*inv*s[t]     + b[t];
    yr[t+256] = d1*inv*s[t+256] + b[t+256];
    yr[t+512] = d2*inv*s[t+512] + b[t+512];
}

// ---------------- kernel 6: SGEMM ----------------
template<int ACT>
__global__ void sgemm_kernel(const float* __restrict__ A, const float* __restrict__ B,
                             const float* __restrict__ bias, float* __restrict__ C,
                             int M, int N, int K, int ACCUM) {
    __shared__ float As[16][64];
    __shared__ float Bs[16][64];
    int tid = threadIdx.x;
    int tx = tid & 15, ty = tid >> 4;
    int blockRow = blockIdx.y * 64;
    int blockCol = blockIdx.x * 64;
    float acc[4][4] = {};

    for (int k0 = 0; k0 < K; k0 += 16) {
        #pragma unroll
        for (int t = tid; t < 64*16; t += 256) {
            int m  = t >> 4, kk  = t & 15;
            int gr = blockRow + m, gc = k0 + kk;
            As[kk][m] = (gr < M && gc < K) ? A[(size_t)gr*K + gc] : 0.f;
            int kk2 = t >> 6, nn = t & 63;
            int gr2 = k0 + kk2, gc2 = blockCol + nn;
            Bs[kk2][nn] = (gr2 < K && gc2 < N) ? B[(size_t)gr2*N + gc2] : 0.f;
        }
        __syncthreads();
        #pragma unroll
        for (int kk = 0; kk < 16; kk++) {
            float a[4], bb[4];
            #pragma unroll
            for (int i = 0; i < 4; i++) a[i]  = As[kk][ty*4 + i];
            #pragma unroll
            for (int j = 0; j < 4; j++) bb[j] = Bs[kk][tx*4 + j];
            #pragma unroll
            for (int i = 0; i < 4; i++)
                #pragma unroll
                for (int j = 0; j < 4; j++)
                    acc[i][j] += a[i] * bb[j];
        }
        __syncthreads();
    }

    #pragma unroll
    for (int i = 0; i < 4; i++) {
        int r = blockRow + ty*4 + i;
        if (r >= M) continue;
        #pragma unroll
        for (int j = 0; j < 4; j++) {
            int cc = blockCol + tx*4 + j;
            if (cc >= N) continue;
            float v = acc[i][j] + (bias ? bias[cc] : 0.f);
            if (ACT == 1) v = 0.5f * v * (1.0f + erff(v * 0.70710678118654752f));
            if (ACT == 2) v = fmaxf(v, 0.f);
            size_t oi = (size_t)r * N + cc;
            if (ACCUM) C[oi] += v; else C[oi] = v;
        }
    }
}

// ---------------- kernel 7: attention ----------------
#define QT 8
#define SCP 208
#define ATTN_SMEM_FLOATS (TOKS*HD*2 + QT*HD + QT*SCP + 16)
__global__ void attn_kernel() {
    extern __shared__ float sm[];
    float* Ks = sm;
    float* Vs = Ks + TOKS*HD;
    float* Qs = Vs + TOKS*HD;
    float* Sc = Qs + QT*HD;
    float* rowinv = Sc + QT*SCP;

    int bh = blockIdx.x;
    int b = bh / NHEAD, h = bh % NHEAD;
    int tid = threadIdx.x;
    const float* base = g_qkv + (size_t)b * TOKS * (3*Dm) + h * HD;

    for (int i = tid; i < TOKS*HD; i += 256) {
        int t = i >> 6, d = i & 63;
        Ks[i] = base[(size_t)t*(3*Dm) + Dm   + d];
        Vs[i] = base[(size_t)t*(3*Dm) + 2*Dm + d];
    }
    __syncthreads();

    for (int q0 = 0; q0 < TOKS; q0 += QT) {
        int qn = min(QT, TOKS - q0);
        for (int i = tid; i < qn*HD; i += 256) {
            int qi = i >> 6, d = i & 63;
            Qs[qi*HD + d] = base[(size_t)(q0 + qi)*(3*Dm) + d];
        }
        __syncthreads();
        for (int idx = tid; idx < qn*TOKS; idx += 256) {
            int qi = idx / TOKS, j = idx % TOKS;
            const float* kr = Ks + j*HD;
            const float* qr = Qs + qi*HD;
            float s = 0.f;
            #pragma unroll
            for (int d = 0; d < HD; d++) s += qr[d] * kr[d];
            Sc[qi*SCP + j] = s * 0.125f;
        }
        __syncthreads();
        {
            int w = tid >> 5, lane = tid & 31;
            if (w < qn) {
                float* row = Sc + w*SCP;
                float lm = -1e30f;
                for (int j = lane; j < TOKS; j += 32) lm = fmaxf(lm, row[j]);
                for (int o = 16; o; o >>= 1) lm = fmaxf(lm, __shfl_xor_sync(0xFFFFFFFFu, lm, o));
                float ls = 0.f;
                for (int j = lane; j < TOKS; j += 32) { float e = expf(row[j] - lm); row[j] = e; ls += e; }
                for (int o = 16; o; o >>= 1) ls += __shfl_xor_sync(0xFFFFFFFFu, ls, o);
                if (lane == 0) rowinv[w] = 1.f / ls;
            }
        }
        __syncthreads();
        for (int idx = tid; idx < qn*HD; idx += 256) {
            int qi = idx >> 6, d = idx & 63;
            const float* row = Sc + qi*SCP;
            float acc = 0.f;
            for (int j = 0; j < TOKS; j++) acc += row[j] * Vs[j*HD + d];
            g_atto[((size_t)b*TOKS + q0 + qi)*Dm + h*HD + d] = acc * rowinv[qi];
        }
        __syncthreads();
    }
}

// ---------------- host ----------------
extern "C" void kernel_launch(void* const* d_in, const int* in_sizes, int n_in,
                              void* d_out, int out_size) {
    const float* x        = (const float*)d_in[0];
    const float* patch_w  = (const float*)d_in[1];
    const float* patch_b  = (const float*)d_in[2];
    const float* cls_tok  = (const float*)d_in[3];
    const float* pos_emb  = (const float*)d_in[4];
    const float* ln1_s    = (const float*)d_in[5];
    const float* ln1_b    = (const float*)d_in[6];
    const float* qkv_w    = (const float*)d_in[7];
    const float* qkv_b    = (const float*)d_in[8];
    const float* proj_w   = (const float*)d_in[9];
    const float* proj_b   = (const float*)d_in[10];
    const float* ln2_s    = (const float*)d_in[11];
    const float* ln2_b    = (const float*)d_in[12];
    const float* mlp1_w   = (const float*)d_in[13];
    const float* mlp1_b   = (const float*)d_in[14];
    const float* mlp2_w   = (const float*)d_in[15];
    const float* mlp2_b   = (const float*)d_in[16];
    const float* lnf_s    = (const float*)d_in[17];
    const float* lnf_b    = (const float*)d_in[18];
    const float* head_w   = (const float*)d_in[19];
    const float* head_b   = (const float*)d_in[20];
    const float* fc1_w    = (const float*)d_in[21];
    const float* fc1_b    = (const float*)d_in[22];
    const float* fc2_w    = (const float*)d_in[23];
    const float* fc2_b    = (const float*)d_in[24];
    float* out = (float*)d_out;

    float *p_patches, *p_ptok, *p_tok, *p_h, *p_mlp, *p_atto, *p_cls, *p_feat, *p_fc1, *p_qkv;
    cudaGetSymbolAddress((void**)&p_patches, g_patches);
    cudaGetSymbolAddress((void**)&p_ptok,    g_ptok);
    cudaGetSymbolAddress((void**)&p_tok,     g_tok);
    cudaGetSymbolAddress((void**)&p_h,       g_h);
    cudaGetSymbolAddress((void**)&p_mlp,     g_mlp);
    cudaGetSymbolAddress((void**)&p_atto,    g_atto);
    cudaGetSymbolAddress((void**)&p_cls,     g_cls);
    cudaGetSymbolAddress((void**)&p_feat,    g_feat);
    cudaGetSymbolAddress((void**)&p_fc1,     g_fc1);
    cudaGetSymbolAddress((void**)&p_qkv,     g_qkv);

    const int ATTN_SMEM = ATTN_SMEM_FLOATS * (int)sizeof(float);
    cudaFuncSetAttribute(attn_kernel, cudaFuncAttributeMaxDynamicSharedMemorySize, ATTN_SMEM);

    // 1) RNG + target (modern x32, randint via key-split — the JAX-source-accurate layout)
    float* target_out = (out_size >= Nb*NFRAG*2*2) ? (out + Nb*NFRAG*2) : nullptr;
    rng_kernel<<<1, 512>>>(target_out);

    // 2) augment -> g_img
    augment_kernel<<<Nb*NFRAG*3, 256>>>(x);

    // 3) patchify
    {
        int total = Nb*NPT*Dm;
        patchify_kernel<<<(total + 255)/256, 256>>>();
    }

    auto gdim = [](int M, int N) { return dim3((unsigned)((N + 63)/64), (unsigned)((M + 63)/64)); };

    // 4) patch embed GEMM + assemble tokens
    sgemm_kernel<0><<<gdim(Nb*NPT, Dm), 256>>>(p_patches, patch_w, patch_b, p_ptok, Nb*NPT, Dm, Dm, 0);
    {
        int total = Nb*TOKS*Dm;
        assemble_kernel<<<(total + 255)/256, 256>>>(cls_tok, pos_emb);
    }

    // 5) transformer layers
    for (int l = 0; l < NL; l++) {
        ln_kernel<<<ROWS, 256>>>(p_tok, Dm, ln1_s + (size_t)l*Dm, ln1_b + (size_t)l*Dm, p_h, Dm);
        sgemm_kernel<0><<<gdim(ROWS, 3*Dm), 256>>>(p_h, qkv_w + (size_t)l*Dm*3*Dm, qkv_b + (size_t)l*3*Dm,
                                                   p_qkv, ROWS, 3*Dm, Dm, 0);
        attn_kernel<<<Nb*NHEAD, 256, ATTN_SMEM>>>();
        sgemm_kernel<0><<<gdim(ROWS, Dm), 256>>>(p_atto, proj_w + (size_t)l*Dm*Dm, proj_b + (size_t)l*Dm,
                                                 p_tok, ROWS, Dm, Dm, 1);
        ln_kernel<<<ROWS, 256>>>(p_tok, Dm, ln2_s + (size_t)l*Dm, ln2_b + (size_t)l*Dm, p_h, Dm);
        sgemm_kernel<1><<<gdim(ROWS, MLPD), 256>>>(p_h, mlp1_w + (size_t)l*Dm*MLPD, mlp1_b + (size_t)l*MLPD,
                                                   p_mlp, ROWS, MLPD, Dm, 0);
        sgemm_kernel<0><<<gdim(ROWS, Dm), 256>>>(p_mlp, mlp2_w + (size_t)l*MLPD*Dm, mlp2_b + (size_t)l*Dm,
                                                 p_tok, ROWS, Dm, MLPD, 1);
    }

    // 6) head
    ln_kernel<<<Nb, 256>>>(p_tok, (long long)TOKS*Dm, lnf_s, lnf_b, p_cls, Dm);
    sgemm_kernel<0><<<gdim(Nb, NCLS), 256>>>(p_cls, head_w, head_b, p_feat, Nb, NCLS, Dm, 0);
    sgemm_kernel<2><<<gdim(Nb, NCLS), 256>>>(p_feat, fc1_w, fc1_b, p_fc1, Nb, NCLS, NCLS, 0);
    sgemm_kernel<0><<<gdim(Nb, NFRAG*2), 256>>>(p_fc1, fc2_w, fc2_b, out, Nb, NFRAG*2, NCLS, 0);
}

// round 11
// speedup vs baseline: 1.9446x; 1.9446x over previous
#include <cuda_runtime.h>
#include <math.h>

// ---------------- problem constants ----------------
#define Nb    32
#define Pfr   75
#define NGRID 3
#define NFRAG 9
#define CROPS 64
#define PUZ   225
#define IMGS  224
#define PATCH 16
#define NPT   196
#define Dm    768
#define NHEAD 12
#define HD    64
#define NL    12
#define MLPD  3072
#define NCLS  1000
#define TOKS  197
#define ROWS  (Nb*TOKS)   // 6304

// ---------------- scratch (static device globals; no allocation) ----------------
__device__ float g_img[Nb*3*PUZ*PUZ];
__device__ float g_patches[(size_t)Nb*NPT*Dm];
__device__ float g_ptok[(size_t)Nb*NPT*Dm];
__device__ float g_tok[(size_t)ROWS*Dm];
__device__ float g_h[(size_t)ROWS*Dm];
__device__ float g_qkv[(size_t)ROWS*3*Dm];
__device__ float g_atto[(size_t)ROWS*Dm];
__device__ float g_mlp[(size_t)ROWS*MLPD];
__device__ float g_cls[Nb*Dm];
__device__ float g_feat[Nb*NCLS];
__device__ float g_fc1[Nb*NCLS];
__device__ int   g_shuffle[Nb*NFRAG];
__device__ int   g_offs[Nb*NFRAG*2];
__device__ int   g_jitt[Nb*NFRAG*3];

// ---------------- threefry2x32 (KAT-verified core) ----------------
__device__ __forceinline__ void threefry(unsigned k0, unsigned k1, unsigned &x0, unsigned &x1) {
    unsigned ks0 = k0, ks1 = k1, ks2 = k0 ^ k1 ^ 0x1BD11BDAu;
    x0 += ks0; x1 += ks1;
#define TFRND(r) { x0 += x1; x1 = (x1 << (r)) | (x1 >> (32 - (r))); x1 ^= x0; }
    TFRND(13) TFRND(15) TFRND(26) TFRND(6);  x0 += ks1; x1 += ks2 + 1u;
    TFRND(17) TFRND(29) TFRND(16) TFRND(24); x0 += ks2; x1 += ks0 + 2u;
    TFRND(13) TFRND(15) TFRND(26) TFRND(6);  x0 += ks0; x1 += ks1 + 3u;
    TFRND(17) TFRND(29) TFRND(16) TFRND(24); x0 += ks1; x1 += ks2 + 4u;
    TFRND(13) TFRND(15) TFRND(26) TFRND(6);  x0 += ks2; x1 += ks0 + 5u;
#undef TFRND
}

__device__ __forceinline__ unsigned rb32_part(unsigned k0, unsigned k1, unsigned i) {
    unsigned x0 = 0u, x1 = i;
    threefry(k0, k1, x0, x1);
    return x0 ^ x1;
}

__device__ __forceinline__ void split_key(unsigned k0, unsigned k1, unsigned t,
                                          unsigned &o0, unsigned &o1) {
    unsigned x0 = 0u, x1 = t;
    threefry(k0, k1, x0, x1);
    o0 = x0; o1 = x1;
}

// ---------------- kernel 1: RNG setup + target output (modern x32 + split-randint) ----------------
__global__ void rng_kernel(float* target_out) {
    __shared__ unsigned keys[14];
    __shared__ float noise[Nb*NFRAG];
    int tid = threadIdx.x;

    if (tid == 0) {
        for (int t = 0; t < 3; t++)
            split_key(0u, 42u, (unsigned)t, keys[2*t], keys[2*t+1]);
        split_key(keys[2], keys[3], 0u, keys[6],  keys[7]);
        split_key(keys[2], keys[3], 1u, keys[8],  keys[9]);
        split_key(keys[4], keys[5], 0u, keys[10], keys[11]);
        split_key(keys[4], keys[5], 1u, keys[12], keys[13]);
    }
    __syncthreads();

    if (tid < Nb*NFRAG) {
        unsigned bits = rb32_part(keys[0], keys[1], (unsigned)tid);
        noise[tid] = __uint_as_float((bits >> 9) | 0x3F800000u) - 1.0f;
    }
    __syncthreads();

    if (tid < Nb) {
        int ids[NFRAG];
        unsigned used = 0;
        for (int r = 0; r < NFRAG; r++) {
            int best = -1;
            for (int j = 0; j < NFRAG; j++) {
                if (used & (1u << j)) continue;
                if (best < 0 || noise[tid*NFRAG + j] < noise[tid*NFRAG + best]) best = j;
            }
            ids[r] = best; used |= (1u << best);
        }
        int rest[NFRAG];
        for (int r = 0; r < NFRAG; r++) { g_shuffle[tid*NFRAG + r] = ids[r]; rest[ids[r]] = r; }
        if (target_out) {
            for (int f = 0; f < NFRAG; f++) {
                target_out[(tid*NFRAG + f)*2 + 0] = (float)(rest[f] / 3);
                target_out[(tid*NFRAG + f)*2 + 1] = (float)(rest[f] % 3);
            }
        }
    }

    for (int i = tid; i < Nb*NFRAG*2; i += blockDim.x) {
        unsigned hi = rb32_part(keys[6], keys[7], (unsigned)i);
        unsigned lo = rb32_part(keys[8], keys[9], (unsigned)i);
        unsigned v = (((hi % 12u) * 4u) + (lo % 12u)) % 12u;
        g_offs[i] = (int)v;
    }
    for (int i = tid; i < Nb*NFRAG*3; i += blockDim.x) {
        unsigned hi = rb32_part(keys[10], keys[11], (unsigned)i);
        unsigned lo = rb32_part(keys[12], keys[13], (unsigned)i);
        unsigned v = ((hi % 5u) + (lo % 5u)) % 5u;
        g_jitt[i] = (int)v - 2;
    }
}

// ---------------- block reductions (blockDim == 256) ----------------
__device__ __forceinline__ float bsum256(float v, float* red8) {
    for (int o = 16; o; o >>= 1) v += __shfl_xor_sync(0xFFFFFFFFu, v, o);
    if ((threadIdx.x & 31) == 0) red8[threadIdx.x >> 5] = v;
    __syncthreads();
    float r = red8[0]+red8[1]+red8[2]+red8[3]+red8[4]+red8[5]+red8[6]+red8[7];
    __syncthreads();
    return r;
}

// ---------------- kernel 2: augment ----------------
__global__ void augment_kernel(const float* __restrict__ x) {
    __shared__ float buf[Pfr*Pfr];
    __shared__ float red8[8];
    int bfc = blockIdx.x;
    int c = bfc % 3;
    int bf = bfc / 3;
    int b = bf / NFRAG, f = bf % NFRAG;

    int src = g_shuffle[bf];
    int sr = (src / 3) * Pfr + g_offs[2*bf + 0];
    int sc = (src % 3) * Pfr + g_offs[2*bf + 1];
    float jitv = (float)g_jitt[bf*3 + c];
    const float* xp = x + ((size_t)b*3 + c) * PUZ * PUZ;

    const float sf = 64.0f / 75.0f;
    float lsum = 0.f;
    for (int idx = threadIdx.x; idx < Pfr*Pfr; idx += 256) {
        int i = idx / Pfr, j = idx % Pfr;
        float fy = (i + 0.5f) * sf - 0.5f;
        float fx = (j + 0.5f) * sf - 0.5f;
        int   y0 = (int)floorf(fy); float dy = fy - (float)y0;
        int   x0 = (int)floorf(fx); float dx = fx - (float)x0;
        int y0c = max(0, min(63, y0)),   y1c = max(0, min(63, y0 + 1));
        int x0c = max(0, min(63, x0)),   x1c = max(0, min(63, x0 + 1));
        const float* r0 = xp + (size_t)(sr + y0c) * PUZ + sc;
        const float* r1 = xp + (size_t)(sr + y1c) * PUZ + sc;
        float v = (1.f-dy)*((1.f-dx)*r0[x0c] + dx*r0[x1c])
                +       dy*((1.f-dx)*r1[x0c] + dx*r1[x1c]);
        v = v + jitv;
        v = fminf(fmaxf(v, 0.f), 255.f);
        buf[idx] = v;
        lsum += v;
    }
    float m = bsum256(lsum, red8) * (1.0f / (Pfr*Pfr));
    float lss = 0.f;
    for (int idx = threadIdx.x; idx < Pfr*Pfr; idx += 256) {
        float d = buf[idx] - m;
        lss += d * d;
    }
    float ss = bsum256(lss, red8);
    float s = sqrtf(ss / (float)(Pfr*Pfr - 1));
    if (s == 0.f) s = 1.f;

    int gi = f / 3, gj = f % 3;
    float* op = g_img + ((size_t)b*3 + c) * PUZ * PUZ + (size_t)gi*Pfr*PUZ + gj*Pfr;
    for (int idx = threadIdx.x; idx < Pfr*Pfr; idx += 256) {
        op[(idx / Pfr) * PUZ + (idx % Pfr)] = (buf[idx] - m) / s;
    }
}

// ---------------- kernel 3: patchify ----------------
__global__ void patchify_kernel() {
    int idx = blockIdx.x * blockDim.x + threadIdx.x;
    if (idx >= Nb*NPT*Dm) return;
    int k = idx % Dm;
    int p = (idx / Dm) % NPT;
    int b = idx / (Dm * NPT);
    int c = k >> 8, u = (k >> 4) & 15, v = k & 15;
    int pi = p / 14, pj = p % 14;
    g_patches[idx] = g_img[(((size_t)b*3 + c) * PUZ + (pi*16 + u)) * PUZ + (pj*16 + v)];
}

// ---------------- kernel 4: token assemble ----------------
__global__ void assemble_kernel(const float* __restrict__ clstok, const float* __restrict__ pos) {
    int idx = blockIdx.x * blockDim.x + threadIdx.x;
    if (idx >= Nb*TOKS*Dm) return;
    int d = idx % Dm;
    int t = (idx / Dm) % TOKS;
    int b = idx / (Dm * TOKS);
    float v = (t == 0) ? clstok[d] : g_ptok[((size_t)b*NPT + (t-1))*Dm + d];
    g_tok[idx] = v + pos[t*Dm + d];
}

// ---------------- kernel 5: layernorm ----------------
__global__ void ln_kernel(const float* __restrict__ x, long long sx,
                          const float* __restrict__ s, const float* __restrict__ b,
                          float* __restrict__ y, long long sy) {
    __shared__ float red8[8];
    const float* xr = x + (long long)blockIdx.x * sx;
    float* yr = y + (long long)blockIdx.x * sy;
    int t = threadIdx.x;
    float v0 = xr[t], v1 = xr[t+256], v2 = xr[t+512];
    float m = bsum256(v0+v1+v2, red8) * (1.0f/768.0f);
    float d0 = v0-m, d1 = v1-m, d2 = v2-m;
    float var = bsum256(d0*d0 + d1*d1 + d2*d2, red8) * (1.0f/768.0f);
    float inv = rsqrtf(var + 1e-6f);
    yr[t]     = d0*inv*s[t]     + b[t];
    yr[t+256] = d1*inv*s[t+256] + b[t+256];
    yr[t+512] = d2*inv*s[t+512] + b[t+512];
}

// ---------------- kernel 6a: small fp32 SGEMM (head only) ----------------
template<int ACT>
__global__ void sgemm_kernel(const float* __restrict__ A, const float* __restrict__ B,
                             const float* __restrict__ bias, float* __restrict__ C,
                             int M, int N, int K, int ACCUM) {
    __shared__ float As[16][64];
    __shared__ float Bs[16][64];
    int tid = threadIdx.x;
    int tx = tid & 15, ty = tid >> 4;
    int blockRow = blockIdx.y * 64;
    int blockCol = blockIdx.x * 64;
    float acc[4][4] = {};

    for (int k0 = 0; k0 < K; k0 += 16) {
        #pragma unroll
        for (int t = tid; t < 64*16; t += 256) {
            int m  = t >> 4, kk  = t & 15;
            int gr = blockRow + m, gc = k0 + kk;
            As[kk][m] = (gr < M && gc < K) ? A[(size_t)gr*K + gc] : 0.f;
            int kk2 = t >> 6, nn = t & 63;
            int gr2 = k0 + kk2, gc2 = blockCol + nn;
            Bs[kk2][nn] = (gr2 < K && gc2 < N) ? B[(size_t)gr2*N + gc2] : 0.f;
        }
        __syncthreads();
        #pragma unroll
        for (int kk = 0; kk < 16; kk++) {
            float a[4], bb[4];
            #pragma unroll
            for (int i = 0; i < 4; i++) a[i]  = As[kk][ty*4 + i];
            #pragma unroll
            for (int j = 0; j < 4; j++) bb[j] = Bs[kk][tx*4 + j];
            #pragma unroll
            for (int i = 0; i < 4; i++)
                #pragma unroll
                for (int j = 0; j < 4; j++)
                    acc[i][j] += a[i] * bb[j];
        }
        __syncthreads();
    }

    #pragma unroll
    for (int i = 0; i < 4; i++) {
        int r = blockRow + ty*4 + i;
        if (r >= M) continue;
        #pragma unroll
        for (int j = 0; j < 4; j++) {
            int cc = blockCol + tx*4 + j;
            if (cc >= N) continue;
            float v = acc[i][j] + (bias ? bias[cc] : 0.f);
            if (ACT == 1) v = 0.5f * v * (1.0f + erff(v * 0.70710678118654752f));
            if (ACT == 2) v = fmaxf(v, 0.f);
            size_t oi = (size_t)r * N + cc;
            if (ACCUM) C[oi] += v; else C[oi] = v;
        }
    }
}

// ---------------- kernel 6b: tf32 tensor-core GEMM ----------------
// C[M,N] = act(A[M,K] @ B[K,N] + bias) [+= C]; N%128==0, K%32==0, M arbitrary.
// Block 128x128, BK=32, 256 threads = 8 warps, warp tile 32x64 (2x8 m16n8k8 tiles).
#define GBM 128
#define GBN 128
#define GBK 32
#define ASTRIDE (GBM + 1)    // 129
#define BSTRIDE (GBN + 4)    // 132

__device__ __forceinline__ unsigned f2tf32(float f) {
    unsigned r;
    asm("cvt.rna.tf32.f32 %0, %1;" : "=r"(r) : "f"(f));
    return r;
}

__device__ __forceinline__ void mma_tf32(float* c, const unsigned* a, const unsigned* b) {
    asm volatile(
        "mma.sync.aligned.m16n8k8.row.col.f32.tf32.tf32.f32 "
        "{%0,%1,%2,%3}, {%4,%5,%6,%7}, {%8,%9}, {%0,%1,%2,%3};"
        : "+f"(c[0]), "+f"(c[1]), "+f"(c[2]), "+f"(c[3])
        : "r"(a[0]), "r"(a[1]), "r"(a[2]), "r"(a[3]), "r"(b[0]), "r"(b[1]));
}

template<int ACT>
__global__ __launch_bounds__(256, 1)
void gemm_tf32_kernel(const float* __restrict__ A, const float* __restrict__ B,
                      const float* __restrict__ bias, float* __restrict__ C,
                      int M, int N, int K, int ACCUM) {
    __shared__ unsigned As[GBK * ASTRIDE];   // As[k][m], tf32 bits
    __shared__ unsigned Bs[GBK * BSTRIDE];   // Bs[k][n], tf32 bits

    int tid  = threadIdx.x;
    int lane = tid & 31;
    int warp = tid >> 5;
    int g  = lane >> 2;      // 0..7
    int tg = lane & 3;       // 0..3
    int wm = (warp & 3) * 32;   // warp M offset in block tile
    int wn = (warp >> 2) * 64;  // warp N offset in block tile

    int rowBase = blockIdx.y * GBM;
    int colBase = blockIdx.x * GBN;

    float acc[2][8][4];
    #pragma unroll
    for (int mt = 0; mt < 2; mt++)
        #pragma unroll
        for (int nt = 0; nt < 8; nt++)
            #pragma unroll
            for (int i = 0; i < 4; i++) acc[mt][nt][i] = 0.f;

    // A-tile load mapping: thread -> (m = tid/8 + 32*pass, kq = (tid%8)*4)
    int a_m0 = tid >> 3;
    int a_k0 = (tid & 7) * 4;
    // B-tile load mapping: thread -> (k = tid/32 + 8*pass, n = (tid%32)*4)
    int b_k0 = tid >> 5;
    int b_n0 = (tid & 31) * 4;

    for (int k0 = 0; k0 < K; k0 += GBK) {
        // --- load A tile (128 x 32) ---
        #pragma unroll
        for (int pass = 0; pass < 4; pass++) {
            int m = a_m0 + pass * 32;
            int grow = rowBase + m;
            float4 v;
            if (grow < M) {
                v = *reinterpret_cast<const float4*>(A + (size_t)grow * K + k0 + a_k0);
            } else {
                v = make_float4(0.f, 0.f, 0.f, 0.f);
            }
            As[(a_k0 + 0) * ASTRIDE + m] = f2tf32(v.x);
            As[(a_k0 + 1) * ASTRIDE + m] = f2tf32(v.y);
            As[(a_k0 + 2) * ASTRIDE + m] = f2tf32(v.z);
            As[(a_k0 + 3) * ASTRIDE + m] = f2tf32(v.w);
        }
        // --- load B tile (32 x 128) ---
        #pragma unroll
        for (int pass = 0; pass < 4; pass++) {
            int k = b_k0 + pass * 8;
            const float4 v = *reinterpret_cast<const float4*>(B + (size_t)(k0 + k) * N + colBase + b_n0);
            uint4 w;
            w.x = f2tf32(v.x); w.y = f2tf32(v.y); w.z = f2tf32(v.z); w.w = f2tf32(v.w);
            *reinterpret_cast<uint4*>(&Bs[k * BSTRIDE + b_n0]) = w;
        }
        __syncthreads();

        // --- mma over 4 k-steps of 8 ---
        #pragma unroll
        for (int kk = 0; kk < GBK; kk += 8) {
            unsigned afr[2][4], bfr[8][2];
            #pragma unroll
            for (int mt = 0; mt < 2; mt++) {
                int mbase = wm + mt * 16;
                afr[mt][0] = As[(kk + tg)     * ASTRIDE + mbase + g];
                afr[mt][1] = As[(kk + tg)     * ASTRIDE + mbase + g + 8];
                afr[mt][2] = As[(kk + tg + 4) * ASTRIDE + mbase + g];
                afr[mt][3] = As[(kk + tg + 4) * ASTRIDE + mbase + g + 8];
            }
            #pragma unroll
            for (int nt = 0; nt < 8; nt++) {
                int nbase = wn + nt * 8;
                bfr[nt][0] = Bs[(kk + tg)     * BSTRIDE + nbase + g];
                bfr[nt][1] = Bs[(kk + tg + 4) * BSTRIDE + nbase + g];
            }
            #pragma unroll
            for (int mt = 0; mt < 2; mt++)
                #pragma unroll
                for (int nt = 0; nt < 8; nt++)
                    mma_tf32(acc[mt][nt], afr[mt], bfr[nt]);
        }
        __syncthreads();
    }

    // --- epilogue ---
    #pragma unroll
    for (int mt = 0; mt < 2; mt++) {
        int r1 = rowBase + wm + mt * 16 + g;
        int r2 = r1 + 8;
        #pragma unroll
        for (int nt = 0; nt < 8; nt++) {
            int col = colBase + wn + nt * 8 + tg * 2;
            float bv0 = bias ? bias[col]     : 0.f;
            float bv1 = bias ? bias[col + 1] : 0.f;
            #pragma unroll
            for (int half = 0; half < 2; half++) {
                int r = half ? r2 : r1;
                if (r >= M) continue;
                float v0 = acc[mt][nt][half*2 + 0] + bv0;
                float v1 = acc[mt][nt][half*2 + 1] + bv1;
                if (ACT == 1) {
                    v0 = 0.5f * v0 * (1.0f + erff(v0 * 0.70710678118654752f));
                    v1 = 0.5f * v1 * (1.0f + erff(v1 * 0.70710678118654752f));
                }
                if (ACT == 2) { v0 = fmaxf(v0, 0.f); v1 = fmaxf(v1, 0.f); }
                size_t oi = (size_t)r * N + col;
                if (ACCUM) { C[oi] += v0; C[oi + 1] += v1; }
                else       { C[oi]  = v0; C[oi + 1]  = v1; }
            }
        }
    }
}

// ---------------- kernel 7: attention ----------------
#define QT 8
#define SCP 208
#define ATTN_SMEM_FLOATS (TOKS*HD*2 + QT*HD + QT*SCP + 16)
__global__ void attn_kernel() {
    extern __shared__ float sm[];
    float* Ks = sm;
    float* Vs = Ks + TOKS*HD;
    float* Qs = Vs + TOKS*HD;
    float* Sc = Qs + QT*HD;
    float* rowinv = Sc + QT*SCP;

    int bh = blockIdx.x;
    int b = bh / NHEAD, h = bh % NHEAD;
    int tid = threadIdx.x;
    const float* base = g_qkv + (size_t)b * TOKS * (3*Dm) + h * HD;

    for (int i = tid; i < TOKS*HD; i += 256) {
        int t = i >> 6, d = i & 63;
        Ks[i] = base[(size_t)t*(3*Dm) + Dm   + d];
        Vs[i] = base[(size_t)t*(3*Dm) + 2*Dm + d];
    }
    __syncthreads();

    for (int q0 = 0; q0 < TOKS; q0 += QT) {
        int qn = min(QT, TOKS - q0);
        for (int i = tid; i < qn*HD; i += 256) {
            int qi = i >> 6, d = i & 63;
            Qs[qi*HD + d] = base[(size_t)(q0 + qi)*(3*Dm) + d];
        }
        __syncthreads();
        for (int idx = tid; idx < qn*TOKS; idx += 256) {
            int qi = idx / TOKS, j = idx % TOKS;
            const float* kr = Ks + j*HD;
            const float* qr = Qs + qi*HD;
            float s = 0.f;
            #pragma unroll
            for (int d = 0; d < HD; d++) s += qr[d] * kr[d];
            Sc[qi*SCP + j] = s * 0.125f;
        }
        __syncthreads();
        {
            int w = tid >> 5, lane = tid & 31;
            if (w < qn) {
                float* row = Sc + w*SCP;
                float lm = -1e30f;
                for (int j = lane; j < TOKS; j += 32) lm = fmaxf(lm, row[j]);
                for (int o = 16; o; o >>= 1) lm = fmaxf(lm, __shfl_xor_sync(0xFFFFFFFFu, lm, o));
                float ls = 0.f;
                for (int j = lane; j < TOKS; j += 32) { float e = expf(row[j] - lm); row[j] = e; ls += e; }
                for (int o = 16; o; o >>= 1) ls += __shfl_xor_sync(0xFFFFFFFFu, ls, o);
                if (lane == 0) rowinv[w] = 1.f / ls;
            }
        }
        __syncthreads();
        for (int idx = tid; idx < qn*HD; idx += 256) {
            int qi = idx >> 6, d = idx & 63;
            const float* row = Sc + qi*SCP;
            float acc = 0.f;
            for (int j = 0; j < TOKS; j++) acc += row[j] * Vs[j*HD + d];
            g_atto[((size_t)b*TOKS + q0 + qi)*Dm + h*HD + d] = acc * rowinv[qi];
        }
        __syncthreads();
    }
}

// ---------------- host ----------------
extern "C" void kernel_launch(void* const* d_in, const int* in_sizes, int n_in,
                              void* d_out, int out_size) {
    const float* x        = (const float*)d_in[0];
    const float* patch_w  = (const float*)d_in[1];
    const float* patch_b  = (const float*)d_in[2];
    const float* cls_tok  = (const float*)d_in[3];
    const float* pos_emb  = (const float*)d_in[4];
    const float* ln1_s    = (const float*)d_in[5];
    const float* ln1_b    = (const float*)d_in[6];
    const float* qkv_w    = (const float*)d_in[7];
    const float* qkv_b    = (const float*)d_in[8];
    const float* proj_w   = (const float*)d_in[9];
    const float* proj_b   = (const float*)d_in[10];
    const float* ln2_s    = (const float*)d_in[11];
    const float* ln2_b    = (const float*)d_in[12];
    const float* mlp1_w   = (const float*)d_in[13];
    const float* mlp1_b   = (const float*)d_in[14];
    const float* mlp2_w   = (const float*)d_in[15];
    const float* mlp2_b   = (const float*)d_in[16];
    const float* lnf_s    = (const float*)d_in[17];
    const float* lnf_b    = (const float*)d_in[18];
    const float* head_w   = (const float*)d_in[19];
    const float* head_b   = (const float*)d_in[20];
    const float* fc1_w    = (const float*)d_in[21];
    const float* fc1_b    = (const float*)d_in[22];
    const float* fc2_w    = (const float*)d_in[23];
    const float* fc2_b    = (const float*)d_in[24];
    float* out = (float*)d_out;

    float *p_patches, *p_ptok, *p_tok, *p_h, *p_mlp, *p_atto, *p_cls, *p_feat, *p_fc1, *p_qkv;
    cudaGetSymbolAddress((void**)&p_patches, g_patches);
    cudaGetSymbolAddress((void**)&p_ptok,    g_ptok);
    cudaGetSymbolAddress((void**)&p_tok,     g_tok);
    cudaGetSymbolAddress((void**)&p_h,       g_h);
    cudaGetSymbolAddress((void**)&p_mlp,     g_mlp);
    cudaGetSymbolAddress((void**)&p_atto,    g_atto);
    cudaGetSymbolAddress((void**)&p_cls,     g_cls);
    cudaGetSymbolAddress((void**)&p_feat,    g_feat);
    cudaGetSymbolAddress((void**)&p_fc1,     g_fc1);
    cudaGetSymbolAddress((void**)&p_qkv,     g_qkv);

    const int ATTN_SMEM = ATTN_SMEM_FLOATS * (int)sizeof(float);
    cudaFuncSetAttribute(attn_kernel, cudaFuncAttributeMaxDynamicSharedMemorySize, ATTN_SMEM);

    // 1) RNG + target
    float* target_out = (out_size >= Nb*NFRAG*2*2) ? (out + Nb*NFRAG*2) : nullptr;
    rng_kernel<<<1, 512>>>(target_out);

    // 2) augment -> g_img
    augment_kernel<<<Nb*NFRAG*3, 256>>>(x);

    // 3) patchify
    {
        int total = Nb*NPT*Dm;
        patchify_kernel<<<(total + 255)/256, 256>>>();
    }

    auto g64  = [](int M, int N) { return dim3((unsigned)((N + 63)/64),  (unsigned)((M + 63)/64)); };
    auto g128 = [](int M, int N) { return dim3((unsigned)(N/128), (unsigned)((M + 127)/128)); };

    // 4) patch embed GEMM (tf32) + assemble tokens
    gemm_tf32_kernel<0><<<g128(Nb*NPT, Dm), 256>>>(p_patches, patch_w, patch_b, p_ptok, Nb*NPT, Dm, Dm, 0);
    {
        int total = Nb*TOKS*Dm;
        assemble_kernel<<<(total + 255)/256, 256>>>(cls_tok, pos_emb);
    }

    // 5) transformer layers (all big GEMMs on tensor cores, tf32)
    for (int l = 0; l < NL; l++) {
        ln_kernel<<<ROWS, 256>>>(p_tok, Dm, ln1_s + (size_t)l*Dm, ln1_b + (size_t)l*Dm, p_h, Dm);
        gemm_tf32_kernel<0><<<g128(ROWS, 3*Dm), 256>>>(p_h, qkv_w + (size_t)l*Dm*3*Dm, qkv_b + (size_t)l*3*Dm,
                                                       p_qkv, ROWS, 3*Dm, Dm, 0);
        attn_kernel<<<Nb*NHEAD, 256, ATTN_SMEM>>>();
        gemm_tf32_kernel<0><<<g128(ROWS, Dm), 256>>>(p_atto, proj_w + (size_t)l*Dm*Dm, proj_b + (size_t)l*Dm,
                                                     p_tok, ROWS, Dm, Dm, 1);
        ln_kernel<<<ROWS, 256>>>(p_tok, Dm, ln2_s + (size_t)l*Dm, ln2_b + (size_t)l*Dm, p_h, Dm);
        gemm_tf32_kernel<1><<<g128(ROWS, MLPD), 256>>>(p_h, mlp1_w + (size_t)l*Dm*MLPD, mlp1_b + (size_t)l*MLPD,
                                                       p_mlp, ROWS, MLPD, Dm, 0);
        gemm_tf32_kernel<0><<<g128(ROWS, Dm), 256>>>(p_mlp, mlp2_w + (size_t)l*MLPD*Dm, mlp2_b + (size_t)l*Dm,
                                                     p_tok, ROWS, Dm, MLPD, 1);
    }

    // 6) head (small GEMMs on fp32 path)
    ln_kernel<<<Nb, 256>>>(p_tok, (long long)TOKS*Dm, lnf_s, lnf_b, p_cls, Dm);
    sgemm_kernel<0><<<g64(Nb, NCLS), 256>>>(p_cls, head_w, head_b, p_feat, Nb, NCLS, Dm, 0);
    sgemm_kernel<2><<<g64(Nb, NCLS), 256>>>(p_feat, fc1_w, fc1_b, p_fc1, Nb, NCLS, NCLS, 0);
    sgemm_kernel<0><<<g64(Nb, NFRAG*2), 256>>>(p_fc1, fc2_w, fc2_b, out, Nb, NFRAG*2, NCLS, 0);
}

// round 12
// speedup vs baseline: 2.2311x; 1.1473x over previous
#include <cuda_runtime.h>
#include <math.h>

// ---------------- problem constants ----------------
#define Nb    32
#define Pfr   75
#define NGRID 3
#define NFRAG 9
#define CROPS 64
#define PUZ   225
#define IMGS  224
#define PATCH 16
#define NPT   196
#define Dm    768
#define NHEAD 12
#define HD    64
#define NL    12
#define MLPD  3072
#define NCLS  1000
#define TOKS  197
#define ROWS  (Nb*TOKS)   // 6304

// ---------------- scratch (static device globals; no allocation) ----------------
__device__ float g_img[Nb*3*PUZ*PUZ];
__device__ float g_patches[(size_t)Nb*NPT*Dm];
__device__ float g_ptok[(size_t)Nb*NPT*Dm];
__device__ float g_tok[(size_t)ROWS*Dm];
__device__ float g_h[(size_t)ROWS*Dm];
__device__ float g_qkv[(size_t)ROWS*3*Dm];
__device__ float g_atto[(size_t)ROWS*Dm];
__device__ float g_mlp[(size_t)ROWS*MLPD];
__device__ float g_cls[Nb*Dm];
__device__ float g_feat[Nb*NCLS];
__device__ float g_fc1[Nb*NCLS];
__device__ int   g_shuffle[Nb*NFRAG];
__device__ int   g_offs[Nb*NFRAG*2];
__device__ int   g_jitt[Nb*NFRAG*3];

// ---------------- threefry2x32 (KAT-verified core) ----------------
__device__ __forceinline__ void threefry(unsigned k0, unsigned k1, unsigned &x0, unsigned &x1) {
    unsigned ks0 = k0, ks1 = k1, ks2 = k0 ^ k1 ^ 0x1BD11BDAu;
    x0 += ks0; x1 += ks1;
#define TFRND(r) { x0 += x1; x1 = (x1 << (r)) | (x1 >> (32 - (r))); x1 ^= x0; }
    TFRND(13) TFRND(15) TFRND(26) TFRND(6);  x0 += ks1; x1 += ks2 + 1u;
    TFRND(17) TFRND(29) TFRND(16) TFRND(24); x0 += ks2; x1 += ks0 + 2u;
    TFRND(13) TFRND(15) TFRND(26) TFRND(6);  x0 += ks0; x1 += ks1 + 3u;
    TFRND(17) TFRND(29) TFRND(16) TFRND(24); x0 += ks1; x1 += ks2 + 4u;
    TFRND(13) TFRND(15) TFRND(26) TFRND(6);  x0 += ks2; x1 += ks0 + 5u;
#undef TFRND
}

__device__ __forceinline__ unsigned rb32_part(unsigned k0, unsigned k1, unsigned i) {
    unsigned x0 = 0u, x1 = i;
    threefry(k0, k1, x0, x1);
    return x0 ^ x1;
}

__device__ __forceinline__ void split_key(unsigned k0, unsigned k1, unsigned t,
                                          unsigned &o0, unsigned &o1) {
    unsigned x0 = 0u, x1 = t;
    threefry(k0, k1, x0, x1);
    o0 = x0; o1 = x1;
}

// ---------------- kernel 1: RNG setup + target output ----------------
__global__ void rng_kernel(float* target_out) {
    __shared__ unsigned keys[14];
    __shared__ float noise[Nb*NFRAG];
    int tid = threadIdx.x;

    if (tid == 0) {
        for (int t = 0; t < 3; t++)
            split_key(0u, 42u, (unsigned)t, keys[2*t], keys[2*t+1]);
        split_key(keys[2], keys[3], 0u, keys[6],  keys[7]);
        split_key(keys[2], keys[3], 1u, keys[8],  keys[9]);
        split_key(keys[4], keys[5], 0u, keys[10], keys[11]);
        split_key(keys[4], keys[5], 1u, keys[12], keys[13]);
    }
    __syncthreads();

    if (tid < Nb*NFRAG) {
        unsigned bits = rb32_part(keys[0], keys[1], (unsigned)tid);
        noise[tid] = __uint_as_float((bits >> 9) | 0x3F800000u) - 1.0f;
    }
    __syncthreads();

    if (tid < Nb) {
        int ids[NFRAG];
        unsigned used = 0;
        for (int r = 0; r < NFRAG; r++) {
            int best = -1;
            for (int j = 0; j < NFRAG; j++) {
                if (used & (1u << j)) continue;
                if (best < 0 || noise[tid*NFRAG + j] < noise[tid*NFRAG + best]) best = j;
            }
            ids[r] = best; used |= (1u << best);
        }
        int rest[NFRAG];
        for (int r = 0; r < NFRAG; r++) { g_shuffle[tid*NFRAG + r] = ids[r]; rest[ids[r]] = r; }
        if (target_out) {
            for (int f = 0; f < NFRAG; f++) {
                target_out[(tid*NFRAG + f)*2 + 0] = (float)(rest[f] / 3);
                target_out[(tid*NFRAG + f)*2 + 1] = (float)(rest[f] % 3);
            }
        }
    }

    for (int i = tid; i < Nb*NFRAG*2; i += blockDim.x) {
        unsigned hi = rb32_part(keys[6], keys[7], (unsigned)i);
        unsigned lo = rb32_part(keys[8], keys[9], (unsigned)i);
        unsigned v = (((hi % 12u) * 4u) + (lo % 12u)) % 12u;
        g_offs[i] = (int)v;
    }
    for (int i = tid; i < Nb*NFRAG*3; i += blockDim.x) {
        unsigned hi = rb32_part(keys[10], keys[11], (unsigned)i);
        unsigned lo = rb32_part(keys[12], keys[13], (unsigned)i);
        unsigned v = ((hi % 5u) + (lo % 5u)) % 5u;
        g_jitt[i] = (int)v - 2;
    }
}

// ---------------- block reductions (blockDim == 256) ----------------
__device__ __forceinline__ float bsum256(float v, float* red8) {
    for (int o = 16; o; o >>= 1) v += __shfl_xor_sync(0xFFFFFFFFu, v, o);
    if ((threadIdx.x & 31) == 0) red8[threadIdx.x >> 5] = v;
    __syncthreads();
    float r = red8[0]+red8[1]+red8[2]+red8[3]+red8[4]+red8[5]+red8[6]+red8[7];
    __syncthreads();
    return r;
}

// ---------------- kernel 2: augment ----------------
__global__ void augment_kernel(const float* __restrict__ x) {
    __shared__ float buf[Pfr*Pfr];
    __shared__ float red8[8];
    int bfc = blockIdx.x;
    int c = bfc % 3;
    int bf = bfc / 3;
    int b = bf / NFRAG, f = bf % NFRAG;

    int src = g_shuffle[bf];
    int sr = (src / 3) * Pfr + g_offs[2*bf + 0];
    int sc = (src % 3) * Pfr + g_offs[2*bf + 1];
    float jitv = (float)g_jitt[bf*3 + c];
    const float* xp = x + ((size_t)b*3 + c) * PUZ * PUZ;

    const float sf = 64.0f / 75.0f;
    float lsum = 0.f;
    for (int idx = threadIdx.x; idx < Pfr*Pfr; idx += 256) {
        int i = idx / Pfr, j = idx % Pfr;
        float fy = (i + 0.5f) * sf - 0.5f;
        float fx = (j + 0.5f) * sf - 0.5f;
        int   y0 = (int)floorf(fy); float dy = fy - (float)y0;
        int   x0 = (int)floorf(fx); float dx = fx - (float)x0;
        int y0c = max(0, min(63, y0)),   y1c = max(0, min(63, y0 + 1));
        int x0c = max(0, min(63, x0)),   x1c = max(0, min(63, x0 + 1));
        const float* r0 = xp + (size_t)(sr + y0c) * PUZ + sc;
        const float* r1 = xp + (size_t)(sr + y1c) * PUZ + sc;
        float v = (1.f-dy)*((1.f-dx)*r0[x0c] + dx*r0[x1c])
                +       dy*((1.f-dx)*r1[x0c] + dx*r1[x1c]);
        v = v + jitv;
        v = fminf(fmaxf(v, 0.f), 255.f);
        buf[idx] = v;
        lsum += v;
    }
    float m = bsum256(lsum, red8) * (1.0f / (Pfr*Pfr));
    float lss = 0.f;
    for (int idx = threadIdx.x; idx < Pfr*Pfr; idx += 256) {
        float d = buf[idx] - m;
        lss += d * d;
    }
    float ss = bsum256(lss, red8);
    float s = sqrtf(ss / (float)(Pfr*Pfr - 1));
    if (s == 0.f) s = 1.f;

    int gi = f / 3, gj = f % 3;
    float* op = g_img + ((size_t)b*3 + c) * PUZ * PUZ + (size_t)gi*Pfr*PUZ + gj*Pfr;
    for (int idx = threadIdx.x; idx < Pfr*Pfr; idx += 256) {
        op[(idx / Pfr) * PUZ + (idx % Pfr)] = (buf[idx] - m) / s;
    }
}

// ---------------- kernel 3: patchify ----------------
__global__ void patchify_kernel() {
    int idx = blockIdx.x * blockDim.x + threadIdx.x;
    if (idx >= Nb*NPT*Dm) return;
    int k = idx % Dm;
    int p = (idx / Dm) % NPT;
    int b = idx / (Dm * NPT);
    int c = k >> 8, u = (k >> 4) & 15, v = k & 15;
    int pi = p / 14, pj = p % 14;
    g_patches[idx] = g_img[(((size_t)b*3 + c) * PUZ + (pi*16 + u)) * PUZ + (pj*16 + v)];
}

// ---------------- kernel 4: token assemble ----------------
__global__ void assemble_kernel(const float* __restrict__ clstok, const float* __restrict__ pos) {
    int idx = blockIdx.x * blockDim.x + threadIdx.x;
    if (idx >= Nb*TOKS*Dm) return;
    int d = idx % Dm;
    int t = (idx / Dm) % TOKS;
    int b = idx / (Dm * TOKS);
    float v = (t == 0) ? clstok[d] : g_ptok[((size_t)b*NPT + (t-1))*Dm + d];
    g_tok[idx] = v + pos[t*Dm + d];
}

// ---------------- kernel 5: layernorm ----------------
__global__ void ln_kernel(const float* __restrict__ x, long long sx,
                          const float* __restrict__ s, const float* __restrict__ b,
                          float* __restrict__ y, long long sy) {
    __shared__ float red8[8];
    const float* xr = x + (long long)blockIdx.x * sx;
    float* yr = y + (long long)blockIdx.x * sy;
    int t = threadIdx.x;
    float v0 = xr[t], v1 = xr[t+256], v2 = xr[t+512];
    float m = bsum256(v0+v1+v2, red8) * (1.0f/768.0f);
    float d0 = v0-m, d1 = v1-m, d2 = v2-m;
    float var = bsum256(d0*d0 + d1*d1 + d2*d2, red8) * (1.0f/768.0f);
    float inv = rsqrtf(var + 1e-6f);
    yr[t]     = d0*inv*s[t]     + b[t];
    yr[t+256] = d1*inv*s[t+256] + b[t+256];
    yr[t+512] = d2*inv*s[t+512] + b[t+512];
}

// ---------------- kernel 6a: small fp32 SGEMM (head only) ----------------
template<int ACT>
__global__ void sgemm_kernel(const float* __restrict__ A, const float* __restrict__ B,
                             const float* __restrict__ bias, float* __restrict__ C,
                             int M, int N, int K, int ACCUM) {
    __shared__ float As[16][64];
    __shared__ float Bs[16][64];
    int tid = threadIdx.x;
    int tx = tid & 15, ty = tid >> 4;
    int blockRow = blockIdx.y * 64;
    int blockCol = blockIdx.x * 64;
    float acc[4][4] = {};

    for (int k0 = 0; k0 < K; k0 += 16) {
        #pragma unroll
        for (int t = tid; t < 64*16; t += 256) {
            int m  = t >> 4, kk  = t & 15;
            int gr = blockRow + m, gc = k0 + kk;
            As[kk][m] = (gr < M && gc < K) ? A[(size_t)gr*K + gc] : 0.f;
            int kk2 = t >> 6, nn = t & 63;
            int gr2 = k0 + kk2, gc2 = blockCol + nn;
            Bs[kk2][nn] = (gr2 < K && gc2 < N) ? B[(size_t)gr2*N + gc2] : 0.f;
        }
        __syncthreads();
        #pragma unroll
        for (int kk = 0; kk < 16; kk++) {
            float a[4], bb[4];
            #pragma unroll
            for (int i = 0; i < 4; i++) a[i]  = As[kk][ty*4 + i];
            #pragma unroll
            for (int j = 0; j < 4; j++) bb[j] = Bs[kk][tx*4 + j];
            #pragma unroll
            for (int i = 0; i < 4; i++)
                #pragma unroll
                for (int j = 0; j < 4; j++)
                    acc[i][j] += a[i] * bb[j];
        }
        __syncthreads();
    }

    #pragma unroll
    for (int i = 0; i < 4; i++) {
        int r = blockRow + ty*4 + i;
        if (r >= M) continue;
        #pragma unroll
        for (int j = 0; j < 4; j++) {
            int cc = blockCol + tx*4 + j;
            if (cc >= N) continue;
            float v = acc[i][j] + (bias ? bias[cc] : 0.f);
            if (ACT == 1) v = 0.5f * v * (1.0f + erff(v * 0.70710678118654752f));
            if (ACT == 2) v = fmaxf(v, 0.f);
            size_t oi = (size_t)r * N + cc;
            if (ACCUM) C[oi] += v; else C[oi] = v;
        }
    }
}

// ---------------- kernel 6b: 3xTF32 tensor-core GEMM, reg-double-buffered ----------------
// C[M,N] = act(A[M,K] @ B[K,N] + bias) [+= C]; N%128==0, K%32==0, M arbitrary.
#define GBM 128
#define GBN 128
#define GBK 32
#define ASTRIDE (GBM + 1)    // 129
#define BSTRIDE (GBN + 4)    // 132

__device__ __forceinline__ unsigned f2tf32(float f) {
    unsigned r;
    asm("cvt.rna.tf32.f32 %0, %1;" : "=r"(r) : "f"(f));
    return r;
}

__device__ __forceinline__ void mma_tf32(float* c, const unsigned* a, const unsigned* b) {
    asm volatile(
        "mma.sync.aligned.m16n8k8.row.col.f32.tf32.tf32.f32 "
        "{%0,%1,%2,%3}, {%4,%5,%6,%7}, {%8,%9}, {%0,%1,%2,%3};"
        : "+f"(c[0]), "+f"(c[1]), "+f"(c[2]), "+f"(c[3])
        : "r"(a[0]), "r"(a[1]), "r"(a[2]), "r"(a[3]), "r"(b[0]), "r"(b[1]));
}

template<int ACT>
__global__ __launch_bounds__(256, 1)
void gemm_tf32_kernel(const float* __restrict__ A, const float* __restrict__ B,
                      const float* __restrict__ bias, float* __restrict__ C,
                      int M, int N, int K, int ACCUM) {
    __shared__ unsigned AsH[GBK * ASTRIDE];
    __shared__ unsigned AsL[GBK * ASTRIDE];
    __shared__ unsigned BsH[GBK * BSTRIDE];
    __shared__ unsigned BsL[GBK * BSTRIDE];

    int tid  = threadIdx.x;
    int lane = tid & 31;
    int warp = tid >> 5;
    int g  = lane >> 2;
    int tg = lane & 3;
    int wm = (warp & 3) * 32;
    int wn = (warp >> 2) * 64;

    int rowBase = blockIdx.y * GBM;
    int colBase = blockIdx.x * GBN;

    float acc[2][8][4];
    #pragma unroll
    for (int mt = 0; mt < 2; mt++)
        #pragma unroll
        for (int nt = 0; nt < 8; nt++)
            #pragma unroll
            for (int i = 0; i < 4; i++) acc[mt][nt][i] = 0.f;

    int a_m0 = tid >> 3;
    int a_k0 = (tid & 7) * 4;
    int b_k0 = tid >> 5;
    int b_n0 = (tid & 31) * 4;

    float4 rA[4], rB[4];

    // prologue load tile 0
    #pragma unroll
    for (int pass = 0; pass < 4; pass++) {
        int grow = rowBase + a_m0 + pass * 32;
        rA[pass] = (grow < M) ? *reinterpret_cast<const float4*>(A + (size_t)grow * K + a_k0)
                              : make_float4(0.f, 0.f, 0.f, 0.f);
        int k = b_k0 + pass * 8;
        rB[pass] = *reinterpret_cast<const float4*>(B + (size_t)k * N + colBase + b_n0);
    }

    int nIter = K / GBK;
    for (int it = 0; it < nIter; it++) {
        // store current regs -> smem (hi/lo split)
        #pragma unroll
        for (int pass = 0; pass < 4; pass++) {
            int m = a_m0 + pass * 32;
            float v[4] = {rA[pass].x, rA[pass].y, rA[pass].z, rA[pass].w};
            #pragma unroll
            for (int q = 0; q < 4; q++) {
                unsigned hb = f2tf32(v[q]);
                AsH[(a_k0 + q) * ASTRIDE + m] = hb;
                AsL[(a_k0 + q) * ASTRIDE + m] = __float_as_uint(v[q] - __uint_as_float(hb));
            }
            int k = b_k0 + pass * 8;
            float w[4] = {rB[pass].x, rB[pass].y, rB[pass].z, rB[pass].w};
            uint4 wh, wl;
            wh.x = f2tf32(w[0]); wl.x = __float_as_uint(w[0] - __uint_as_float(wh.x));
            wh.y = f2tf32(w[1]); wl.y = __float_as_uint(w[1] - __uint_as_float(wh.y));
            wh.z = f2tf32(w[2]); wl.z = __float_as_uint(w[2] - __uint_as_float(wh.z));
            wh.w = f2tf32(w[3]); wl.w = __float_as_uint(w[3] - __uint_as_float(wh.w));
            *reinterpret_cast<uint4*>(&BsH[k * BSTRIDE + b_n0]) = wh;
            *reinterpret_cast<uint4*>(&BsL[k * BSTRIDE + b_n0]) = wl;
        }
        __syncthreads();

        // prefetch next tile into regs (LDG in flight during MMA)
        if (it + 1 < nIter) {
            int k0n = (it + 1) * GBK;
            #pragma unroll
            for (int pass = 0; pass < 4; pass++) {
                int grow = rowBase + a_m0 + pass * 32;
                rA[pass] = (grow < M) ? *reinterpret_cast<const float4*>(A + (size_t)grow * K + k0n + a_k0)
                                      : make_float4(0.f, 0.f, 0.f, 0.f);
                int k = b_k0 + pass * 8;
                rB[pass] = *reinterpret_cast<const float4*>(B + (size_t)(k0n + k) * N + colBase + b_n0);
            }
        }

        // MMAs on smem tile
        #pragma unroll
        for (int kk = 0; kk < GBK; kk += 8) {
            unsigned ah[2][4], al[2][4], bh[8][2], bl[8][2];
            #pragma unroll
            for (int mt = 0; mt < 2; mt++) {
                int mbase = wm + mt * 16;
                int r0 = (kk + tg) * ASTRIDE + mbase;
                int r1 = (kk + tg + 4) * ASTRIDE + mbase;
                ah[mt][0] = AsH[r0 + g];  ah[mt][1] = AsH[r0 + g + 8];
                ah[mt][2] = AsH[r1 + g];  ah[mt][3] = AsH[r1 + g + 8];
                al[mt][0] = AsL[r0 + g];  al[mt][1] = AsL[r0 + g + 8];
                al[mt][2] = AsL[r1 + g];  al[mt][3] = AsL[r1 + g + 8];
            }
            #pragma unroll
            for (int nt = 0; nt < 8; nt++) {
                int nbase = wn + nt * 8;
                bh[nt][0] = BsH[(kk + tg)     * BSTRIDE + nbase + g];
                bh[nt][1] = BsH[(kk + tg + 4) * BSTRIDE + nbase + g];
                bl[nt][0] = BsL[(kk + tg)     * BSTRIDE + nbase + g];
                bl[nt][1] = BsL[(kk + tg + 4) * BSTRIDE + nbase + g];
            }
            #pragma unroll
            for (int mt = 0; mt < 2; mt++)
                #pragma unroll
                for (int nt = 0; nt < 8; nt++) {
                    mma_tf32(acc[mt][nt], ah[mt], bh[nt]);   // hi*hi
                    mma_tf32(acc[mt][nt], ah[mt], bl[nt]);   // hi*lo
                    mma_tf32(acc[mt][nt], al[mt], bh[nt]);   // lo*hi
                }
        }
        __syncthreads();
    }

    // epilogue
    #pragma unroll
    for (int mt = 0; mt < 2; mt++) {
        int r1 = rowBase + wm + mt * 16 + g;
        int r2 = r1 + 8;
        #pragma unroll
        for (int nt = 0; nt < 8; nt++) {
            int col = colBase + wn + nt * 8 + tg * 2;
            float bv0 = bias ? bias[col]     : 0.f;
            float bv1 = bias ? bias[col + 1] : 0.f;
            #pragma unroll
            for (int half = 0; half < 2; half++) {
                int r = half ? r2 : r1;
                if (r >= M) continue;
                float v0 = acc[mt][nt][half*2 + 0] + bv0;
                float v1 = acc[mt][nt][half*2 + 1] + bv1;
                if (ACT == 1) {
                    v0 = 0.5f * v0 * (1.0f + erff(v0 * 0.70710678118654752f));
                    v1 = 0.5f * v1 * (1.0f + erff(v1 * 0.70710678118654752f));
                }
                if (ACT == 2) { v0 = fmaxf(v0, 0.f); v1 = fmaxf(v1, 0.f); }
                size_t oi = (size_t)r * N + col;
                if (ACCUM) { C[oi] += v0; C[oi + 1] += v1; }
                else       { C[oi]  = v0; C[oi + 1]  = v1; }
            }
        }
    }
}

// ---------------- kernel 7: attention (K transposed in smem, conflict-free) ----------------
#define QT 8
#define SCP 208
#define TOKSP 201   // odd stride -> conflict-free column access
#define ATTN_SMEM_FLOATS (HD*TOKSP + TOKS*HD + QT*HD + QT*SCP + 16)
__global__ void attn_kernel() {
    extern __shared__ float sm[];
    float* Kt = sm;                 // [HD][TOKSP]  (transposed K)
    float* Vs = Kt + HD*TOKSP;      // [TOKS][HD]
    float* Qs = Vs + TOKS*HD;       // [QT][HD]
    float* Sc = Qs + QT*HD;         // [QT][SCP]
    float* rowinv = Sc + QT*SCP;

    int bh = blockIdx.x;
    int b = bh / NHEAD, h = bh % NHEAD;
    int tid = threadIdx.x;
    const float* base = g_qkv + (size_t)b * TOKS * (3*Dm) + h * HD;

    for (int i = tid; i < TOKS*HD; i += 256) {
        int t = i >> 6, d = i & 63;
        Kt[d*TOKSP + t] = base[(size_t)t*(3*Dm) + Dm   + d];
        Vs[i]           = base[(size_t)t*(3*Dm) + 2*Dm + d];
    }
    __syncthreads();

    for (int q0 = 0; q0 < TOKS; q0 += QT) {
        int qn = min(QT, TOKS - q0);
        for (int i = tid; i < qn*HD; i += 256) {
            int qi = i >> 6, d = i & 63;
            Qs[qi*HD + d] = base[(size_t)(q0 + qi)*(3*Dm) + d];
        }
        __syncthreads();
        // scores: lanes sweep j (conflict-free on Kt), Q broadcast
        for (int qi = 0; qi < qn; qi++) {
            const float* qr = Qs + qi*HD;
            for (int j = tid; j < TOKS; j += 256) {
                float s = 0.f;
                #pragma unroll
                for (int d = 0; d < HD; d++) s += qr[d] * Kt[d*TOKSP + j];
                Sc[qi*SCP + j] = s * 0.125f;
            }
        }
        __syncthreads();
        {
            int w = tid >> 5, lane = tid & 31;
            if (w < qn) {
                float* row = Sc + w*SCP;
                float lm = -1e30f;
                for (int j = lane; j < TOKS; j += 32) lm = fmaxf(lm, row[j]);
                for (int o = 16; o; o >>= 1) lm = fmaxf(lm, __shfl_xor_sync(0xFFFFFFFFu, lm, o));
                float ls = 0.f;
                for (int j = lane; j < TOKS; j += 32) { float e = expf(row[j] - lm); row[j] = e; ls += e; }
                for (int o = 16; o; o >>= 1) ls += __shfl_xor_sync(0xFFFFFFFFu, ls, o);
                if (lane == 0) rowinv[w] = 1.f / ls;
            }
        }
        __syncthreads();
        for (int idx = tid; idx < qn*HD; idx += 256) {
            int qi = idx >> 6, d = idx & 63;
            const float* row = Sc + qi*SCP;
            float acc = 0.f;
            #pragma unroll 4
            for (int j = 0; j < TOKS; j++) acc += row[j] * Vs[j*HD + d];
            g_atto[((size_t)b*TOKS + q0 + qi)*Dm + h*HD + d] = acc * rowinv[qi];
        }
        __syncthreads();
    }
}

// ---------------- host ----------------
extern "C" void kernel_launch(void* const* d_in, const int* in_sizes, int n_in,
                              void* d_out, int out_size) {
    const float* x        = (const float*)d_in[0];
    const float* patch_w  = (const float*)d_in[1];
    const float* patch_b  = (const float*)d_in[2];
    const float* cls_tok  = (const float*)d_in[3];
    const float* pos_emb  = (const float*)d_in[4];
    const float* ln1_s    = (const float*)d_in[5];
    const float* ln1_b    = (const float*)d_in[6];
    const float* qkv_w    = (const float*)d_in[7];
    const float* qkv_b    = (const float*)d_in[8];
    const float* proj_w   = (const float*)d_in[9];
    const float* proj_b   = (const float*)d_in[10];
    const float* ln2_s    = (const float*)d_in[11];
    const float* ln2_b    = (const float*)d_in[12];
    const float* mlp1_w   = (const float*)d_in[13];
    const float* mlp1_b   = (const float*)d_in[14];
    const float* mlp2_w   = (const float*)d_in[15];
    const float* mlp2_b   = (const float*)d_in[16];
    const float* lnf_s    = (const float*)d_in[17];
    const float* lnf_b    = (const float*)d_in[18];
    const float* head_w   = (const float*)d_in[19];
    const float* head_b   = (const float*)d_in[20];
    const float* fc1_w    = (const float*)d_in[21];
    const float* fc1_b    = (const float*)d_in[22];
    const float* fc2_w    = (const float*)d_in[23];
    const float* fc2_b    = (const float*)d_in[24];
    float* out = (float*)d_out;

    float *p_patches, *p_ptok, *p_tok, *p_h, *p_mlp, *p_atto, *p_cls, *p_feat, *p_fc1, *p_qkv;
    cudaGetSymbolAddress((void**)&p_patches, g_patches);
    cudaGetSymbolAddress((void**)&p_ptok,    g_ptok);
    cudaGetSymbolAddress((void**)&p_tok,     g_tok);
    cudaGetSymbolAddress((void**)&p_h,       g_h);
    cudaGetSymbolAddress((void**)&p_mlp,     g_mlp);
    cudaGetSymbolAddress((void**)&p_atto,    g_atto);
    cudaGetSymbolAddress((void**)&p_cls,     g_cls);
    cudaGetSymbolAddress((void**)&p_feat,    g_feat);
    cudaGetSymbolAddress((void**)&p_fc1,     g_fc1);
    cudaGetSymbolAddress((void**)&p_qkv,     g_qkv);

    const int ATTN_SMEM = ATTN_SMEM_FLOATS * (int)sizeof(float);
    cudaFuncSetAttribute(attn_kernel, cudaFuncAttributeMaxDynamicSharedMemorySize, ATTN_SMEM);

    // 1) RNG + target
    float* target_out = (out_size >= Nb*NFRAG*2*2) ? (out + Nb*NFRAG*2) : nullptr;
    rng_kernel<<<1, 512>>>(target_out);

    // 2) augment -> g_img
    augment_kernel<<<Nb*NFRAG*3, 256>>>(x);

    // 3) patchify
    {
        int total = Nb*NPT*Dm;
        patchify_kernel<<<(total + 255)/256, 256>>>();
    }

    auto g64  = [](int M, int N) { return dim3((unsigned)((N + 63)/64),  (unsigned)((M + 63)/64)); };
    auto g128 = [](int M, int N) { return dim3((unsigned)(N/128), (unsigned)((M + 127)/128)); };

    // 4) patch embed GEMM (3xTF32) + assemble tokens
    gemm_tf32_kernel<0><<<g128(Nb*NPT, Dm), 256>>>(p_patches, patch_w, patch_b, p_ptok, Nb*NPT, Dm, Dm, 0);
    {
        int total = Nb*TOKS*Dm;
        assemble_kernel<<<(total + 255)/256, 256>>>(cls_tok, pos_emb);
    }

    // 5) transformer layers
    for (int l = 0; l < NL; l++) {
        ln_kernel<<<ROWS, 256>>>(p_tok, Dm, ln1_s + (size_t)l*Dm, ln1_b + (size_t)l*Dm, p_h, Dm);
        gemm_tf32_kernel<0><<<g128(ROWS, 3*Dm), 256>>>(p_h, qkv_w + (size_t)l*Dm*3*Dm, qkv_b + (size_t)l*3*Dm,
                                                       p_qkv, ROWS, 3*Dm, Dm, 0);
        attn_kernel<<<Nb*NHEAD, 256, ATTN_SMEM>>>();
        gemm_tf32_kernel<0><<<g128(ROWS, Dm), 256>>>(p_atto, proj_w + (size_t)l*Dm*Dm, proj_b + (size_t)l*Dm,
                                                     p_tok, ROWS, Dm, Dm, 1);
        ln_kernel<<<ROWS, 256>>>(p_tok, Dm, ln2_s + (size_t)l*Dm, ln2_b + (size_t)l*Dm, p_h, Dm);
        gemm_tf32_kernel<1><<<g128(ROWS, MLPD), 256>>>(p_h, mlp1_w + (size_t)l*Dm*MLPD, mlp1_b + (size_t)l*MLPD,
                                                       p_mlp, ROWS, MLPD, Dm, 0);
        gemm_tf32_kernel<0><<<g128(ROWS, Dm), 256>>>(p_mlp, mlp2_w + (size_t)l*MLPD*Dm, mlp2_b + (size_t)l*Dm,
                                                     p_tok, ROWS, Dm, MLPD, 1);
    }

    // 6) head
    ln_kernel<<<Nb, 256>>>(p_tok, (long long)TOKS*Dm, lnf_s, lnf_b, p_cls, Dm);
    sgemm_kernel<0><<<g64(Nb, NCLS), 256>>>(p_cls, head_w, head_b, p_feat, Nb, NCLS, Dm, 0);
    sgemm_kernel<2><<<g64(Nb, NCLS), 256>>>(p_feat, fc1_w, fc1_b, p_fc1, Nb, NCLS, NCLS, 0);
    sgemm_kernel<0><<<g64(Nb, NFRAG*2), 256>>>(p_fc1, fc2_w, fc2_b, out, Nb, NFRAG*2, NCLS, 0);
}

// round 13
// speedup vs baseline: 2.5519x; 1.1438x over previous
#include <cuda_runtime.h>
#include <math.h>

// ---------------- problem constants ----------------
#define Nb    32
#define Pfr   75
#define NGRID 3
#define NFRAG 9
#define CROPS 64
#define PUZ   225
#define IMGS  224
#define PATCH 16
#define NPT   196
#define Dm    768
#define NHEAD 12
#define HD    64
#define NL    12
#define MLPD  3072
#define NCLS  1000
#define TOKS  197
#define ROWS  (Nb*TOKS)   // 6304

// ---------------- scratch (static device globals; no allocation) ----------------
__device__ float g_img[Nb*3*PUZ*PUZ];
__device__ float g_patches[(size_t)Nb*NPT*Dm];
__device__ float g_ptok[(size_t)Nb*NPT*Dm];
__device__ float g_tok[(size_t)ROWS*Dm];
__device__ float g_h[(size_t)ROWS*Dm];
__device__ float g_qkv[(size_t)ROWS*3*Dm];
__device__ float g_atto[(size_t)ROWS*Dm];
__device__ float g_mlp[(size_t)ROWS*MLPD];
__device__ float g_cls[Nb*Dm];
__device__ float g_feat[Nb*NCLS];
__device__ float g_fc1[Nb*NCLS];
__device__ int   g_shuffle[Nb*NFRAG];
__device__ int   g_offs[Nb*NFRAG*2];
__device__ int   g_jitt[Nb*NFRAG*3];

// ---------------- threefry2x32 (KAT-verified core) ----------------
__device__ __forceinline__ void threefry(unsigned k0, unsigned k1, unsigned &x0, unsigned &x1) {
    unsigned ks0 = k0, ks1 = k1, ks2 = k0 ^ k1 ^ 0x1BD11BDAu;
    x0 += ks0; x1 += ks1;
#define TFRND(r) { x0 += x1; x1 = (x1 << (r)) | (x1 >> (32 - (r))); x1 ^= x0; }
    TFRND(13) TFRND(15) TFRND(26) TFRND(6);  x0 += ks1; x1 += ks2 + 1u;
    TFRND(17) TFRND(29) TFRND(16) TFRND(24); x0 += ks2; x1 += ks0 + 2u;
    TFRND(13) TFRND(15) TFRND(26) TFRND(6);  x0 += ks0; x1 += ks1 + 3u;
    TFRND(17) TFRND(29) TFRND(16) TFRND(24); x0 += ks1; x1 += ks2 + 4u;
    TFRND(13) TFRND(15) TFRND(26) TFRND(6);  x0 += ks2; x1 += ks0 + 5u;
#undef TFRND
}

__device__ __forceinline__ unsigned rb32_part(unsigned k0, unsigned k1, unsigned i) {
    unsigned x0 = 0u, x1 = i;
    threefry(k0, k1, x0, x1);
    return x0 ^ x1;
}

__device__ __forceinline__ void split_key(unsigned k0, unsigned k1, unsigned t,
                                          unsigned &o0, unsigned &o1) {
    unsigned x0 = 0u, x1 = t;
    threefry(k0, k1, x0, x1);
    o0 = x0; o1 = x1;
}

// ---------------- kernel 1: RNG setup + target output ----------------
__global__ void rng_kernel(float* target_out) {
    __shared__ unsigned keys[14];
    __shared__ float noise[Nb*NFRAG];
    int tid = threadIdx.x;

    if (tid == 0) {
        for (int t = 0; t < 3; t++)
            split_key(0u, 42u, (unsigned)t, keys[2*t], keys[2*t+1]);
        split_key(keys[2], keys[3], 0u, keys[6],  keys[7]);
        split_key(keys[2], keys[3], 1u, keys[8],  keys[9]);
        split_key(keys[4], keys[5], 0u, keys[10], keys[11]);
        split_key(keys[4], keys[5], 1u, keys[12], keys[13]);
    }
    __syncthreads();

    if (tid < Nb*NFRAG) {
        unsigned bits = rb32_part(keys[0], keys[1], (unsigned)tid);
        noise[tid] = __uint_as_float((bits >> 9) | 0x3F800000u) - 1.0f;
    }
    __syncthreads();

    if (tid < Nb) {
        int ids[NFRAG];
        unsigned used = 0;
        for (int r = 0; r < NFRAG; r++) {
            int best = -1;
            for (int j = 0; j < NFRAG; j++) {
                if (used & (1u << j)) continue;
                if (best < 0 || noise[tid*NFRAG + j] < noise[tid*NFRAG + best]) best = j;
            }
            ids[r] = best; used |= (1u << best);
        }
        int rest[NFRAG];
        for (int r = 0; r < NFRAG; r++) { g_shuffle[tid*NFRAG + r] = ids[r]; rest[ids[r]] = r; }
        if (target_out) {
            for (int f = 0; f < NFRAG; f++) {
                target_out[(tid*NFRAG + f)*2 + 0] = (float)(rest[f] / 3);
                target_out[(tid*NFRAG + f)*2 + 1] = (float)(rest[f] % 3);
            }
        }
    }

    for (int i = tid; i < Nb*NFRAG*2; i += blockDim.x) {
        unsigned hi = rb32_part(keys[6], keys[7], (unsigned)i);
        unsigned lo = rb32_part(keys[8], keys[9], (unsigned)i);
        unsigned v = (((hi % 12u) * 4u) + (lo % 12u)) % 12u;
        g_offs[i] = (int)v;
    }
    for (int i = tid; i < Nb*NFRAG*3; i += blockDim.x) {
        unsigned hi = rb32_part(keys[10], keys[11], (unsigned)i);
        unsigned lo = rb32_part(keys[12], keys[13], (unsigned)i);
        unsigned v = ((hi % 5u) + (lo % 5u)) % 5u;
        g_jitt[i] = (int)v - 2;
    }
}

// ---------------- block reductions (blockDim == 256) ----------------
__device__ __forceinline__ float bsum256(float v, float* red8) {
    for (int o = 16; o; o >>= 1) v += __shfl_xor_sync(0xFFFFFFFFu, v, o);
    if ((threadIdx.x & 31) == 0) red8[threadIdx.x >> 5] = v;
    __syncthreads();
    float r = red8[0]+red8[1]+red8[2]+red8[3]+red8[4]+red8[5]+red8[6]+red8[7];
    __syncthreads();
    return r;
}

// ---------------- kernel 2: augment ----------------
__global__ void augment_kernel(const float* __restrict__ x) {
    __shared__ float buf[Pfr*Pfr];
    __shared__ float red8[8];
    int bfc = blockIdx.x;
    int c = bfc % 3;
    int bf = bfc / 3;
    int b = bf / NFRAG, f = bf % NFRAG;

    int src = g_shuffle[bf];
    int sr = (src / 3) * Pfr + g_offs[2*bf + 0];
    int sc = (src % 3) * Pfr + g_offs[2*bf + 1];
    float jitv = (float)g_jitt[bf*3 + c];
    const float* xp = x + ((size_t)b*3 + c) * PUZ * PUZ;

    const float sf = 64.0f / 75.0f;
    float lsum = 0.f;
    for (int idx = threadIdx.x; idx < Pfr*Pfr; idx += 256) {
        int i = idx / Pfr, j = idx % Pfr;
        float fy = (i + 0.5f) * sf - 0.5f;
        float fx = (j + 0.5f) * sf - 0.5f;
        int   y0 = (int)floorf(fy); float dy = fy - (float)y0;
        int   x0 = (int)floorf(fx); float dx = fx - (float)x0;
        int y0c = max(0, min(63, y0)),   y1c = max(0, min(63, y0 + 1));
        int x0c = max(0, min(63, x0)),   x1c = max(0, min(63, x0 + 1));
        const float* r0 = xp + (size_t)(sr + y0c) * PUZ + sc;
        const float* r1 = xp + (size_t)(sr + y1c) * PUZ + sc;
        float v = (1.f-dy)*((1.f-dx)*r0[x0c] + dx*r0[x1c])
                +       dy*((1.f-dx)*r1[x0c] + dx*r1[x1c]);
        v = v + jitv;
        v = fminf(fmaxf(v, 0.f), 255.f);
        buf[idx] = v;
        lsum += v;
    }
    float m = bsum256(lsum, red8) * (1.0f / (Pfr*Pfr));
    float lss = 0.f;
    for (int idx = threadIdx.x; idx < Pfr*Pfr; idx += 256) {
        float d = buf[idx] - m;
        lss += d * d;
    }
    float ss = bsum256(lss, red8);
    float s = sqrtf(ss / (float)(Pfr*Pfr - 1));
    if (s == 0.f) s = 1.f;

    int gi = f / 3, gj = f % 3;
    float* op = g_img + ((size_t)b*3 + c) * PUZ * PUZ + (size_t)gi*Pfr*PUZ + gj*Pfr;
    for (int idx = threadIdx.x; idx < Pfr*Pfr; idx += 256) {
        op[(idx / Pfr) * PUZ + (idx % Pfr)] = (buf[idx] - m) / s;
    }
}

// ---------------- kernel 3: patchify ----------------
__global__ void patchify_kernel() {
    int idx = blockIdx.x * blockDim.x + threadIdx.x;
    if (idx >= Nb*NPT*Dm) return;
    int k = idx % Dm;
    int p = (idx / Dm) % NPT;
    int b = idx / (Dm * NPT);
    int c = k >> 8, u = (k >> 4) & 15, v = k & 15;
    int pi = p / 14, pj = p % 14;
    g_patches[idx] = g_img[(((size_t)b*3 + c) * PUZ + (pi*16 + u)) * PUZ + (pj*16 + v)];
}

// ---------------- kernel 4: token assemble ----------------
__global__ void assemble_kernel(const float* __restrict__ clstok, const float* __restrict__ pos) {
    int idx = blockIdx.x * blockDim.x + threadIdx.x;
    if (idx >= Nb*TOKS*Dm) return;
    int d = idx % Dm;
    int t = (idx / Dm) % TOKS;
    int b = idx / (Dm * TOKS);
    float v = (t == 0) ? clstok[d] : g_ptok[((size_t)b*NPT + (t-1))*Dm + d];
    g_tok[idx] = v + pos[t*Dm + d];
}

// ---------------- kernel 5: layernorm ----------------
__global__ void ln_kernel(const float* __restrict__ x, long long sx,
                          const float* __restrict__ s, const float* __restrict__ b,
                          float* __restrict__ y, long long sy) {
    __shared__ float red8[8];
    const float* xr = x + (long long)blockIdx.x * sx;
    float* yr = y + (long long)blockIdx.x * sy;
    int t = threadIdx.x;
    float v0 = xr[t], v1 = xr[t+256], v2 = xr[t+512];
    float m = bsum256(v0+v1+v2, red8) * (1.0f/768.0f);
    float d0 = v0-m, d1 = v1-m, d2 = v2-m;
    float var = bsum256(d0*d0 + d1*d1 + d2*d2, red8) * (1.0f/768.0f);
    float inv = rsqrtf(var + 1e-6f);
    yr[t]     = d0*inv*s[t]     + b[t];
    yr[t+256] = d1*inv*s[t+256] + b[t+256];
    yr[t+512] = d2*inv*s[t+512] + b[t+512];
}

// ---------------- kernel 6a: small fp32 SGEMM (head only) ----------------
template<int ACT>
__global__ void sgemm_kernel(const float* __restrict__ A, const float* __restrict__ B,
                             const float* __restrict__ bias, float* __restrict__ C,
                             int M, int N, int K, int ACCUM) {
    __shared__ float As[16][64];
    __shared__ float Bs[16][64];
    int tid = threadIdx.x;
    int tx = tid & 15, ty = tid >> 4;
    int blockRow = blockIdx.y * 64;
    int blockCol = blockIdx.x * 64;
    float acc[4][4] = {};

    for (int k0 = 0; k0 < K; k0 += 16) {
        #pragma unroll
        for (int t = tid; t < 64*16; t += 256) {
            int m  = t >> 4, kk  = t & 15;
            int gr = blockRow + m, gc = k0 + kk;
            As[kk][m] = (gr < M && gc < K) ? A[(size_t)gr*K + gc] : 0.f;
            int kk2 = t >> 6, nn = t & 63;
            int gr2 = k0 + kk2, gc2 = blockCol + nn;
            Bs[kk2][nn] = (gr2 < K && gc2 < N) ? B[(size_t)gr2*N + gc2] : 0.f;
        }
        __syncthreads();
        #pragma unroll
        for (int kk = 0; kk < 16; kk++) {
            float a[4], bb[4];
            #pragma unroll
            for (int i = 0; i < 4; i++) a[i]  = As[kk][ty*4 + i];
            #pragma unroll
            for (int j = 0; j < 4; j++) bb[j] = Bs[kk][tx*4 + j];
            #pragma unroll
            for (int i = 0; i < 4; i++)
                #pragma unroll
                for (int j = 0; j < 4; j++)
                    acc[i][j] += a[i] * bb[j];
        }
        __syncthreads();
    }

    #pragma unroll
    for (int i = 0; i < 4; i++) {
        int r = blockRow + ty*4 + i;
        if (r >= M) continue;
        #pragma unroll
        for (int j = 0; j < 4; j++) {
            int cc = blockCol + tx*4 + j;
            if (cc >= N) continue;
            float v = acc[i][j] + (bias ? bias[cc] : 0.f);
            if (ACT == 1) v = 0.5f * v * (1.0f + erff(v * 0.70710678118654752f));
            if (ACT == 2) v = fmaxf(v, 0.f);
            size_t oi = (size_t)r * N + cc;
            if (ACCUM) C[oi] += v; else C[oi] = v;
        }
    }
}

// ---------------- kernel 6b: 3xTF32 tensor-core GEMM (fp32 smem, reg split) ----------------
// C[M,N] = act(A[M,K] @ B[K,N] + bias) [+= C]; N%128==0, K%32==0, M arbitrary.
#define GBM 128
#define GBN 128
#define GBK 32
#define ASTRIDE 132    // 132 % 32 == 4 -> fragment reads conflict-free
#define BSTRIDE 132

__device__ __forceinline__ unsigned f2tf32(float f) {
    unsigned r;
    asm("cvt.rna.tf32.f32 %0, %1;" : "=r"(r) : "f"(f));
    return r;
}

__device__ __forceinline__ void mma_tf32(float* c, const unsigned* a, const unsigned* b) {
    asm volatile(
        "mma.sync.aligned.m16n8k8.row.col.f32.tf32.tf32.f32 "
        "{%0,%1,%2,%3}, {%4,%5,%6,%7}, {%8,%9}, {%0,%1,%2,%3};"
        : "+f"(c[0]), "+f"(c[1]), "+f"(c[2]), "+f"(c[3])
        : "r"(a[0]), "r"(a[1]), "r"(a[2]), "r"(a[3]), "r"(b[0]), "r"(b[1]));
}

// split float -> (hi tf32 bits, lo tf32 bits of residual)
__device__ __forceinline__ void hilo(float v, unsigned &h, unsigned &l) {
    h = f2tf32(v);
    l = __float_as_uint(v - __uint_as_float(h));
}

template<int ACT>
__global__ __launch_bounds__(256, 1)
void gemm_tf32_kernel(const float* __restrict__ A, const float* __restrict__ B,
                      const float* __restrict__ bias, float* __restrict__ C,
                      int M, int N, int K, int ACCUM) {
    __shared__ float As[GBK * ASTRIDE];   // As[k][m], fp32
    __shared__ float Bs[GBK * BSTRIDE];   // Bs[k][n], fp32

    int tid  = threadIdx.x;
    int lane = tid & 31;
    int warp = tid >> 5;
    int g  = lane >> 2;
    int tg = lane & 3;
    int wm = (warp & 3) * 32;
    int wn = (warp >> 2) * 64;

    int rowBase = blockIdx.y * GBM;
    int colBase = blockIdx.x * GBN;

    float acc[2][8][4];
    #pragma unroll
    for (int mt = 0; mt < 2; mt++)
        #pragma unroll
        for (int nt = 0; nt < 8; nt++)
            #pragma unroll
            for (int i = 0; i < 4; i++) acc[mt][nt][i] = 0.f;

    int a_m0 = tid >> 3;
    int a_k0 = (tid & 7) * 4;
    int b_k0 = tid >> 5;
    int b_n0 = (tid & 31) * 4;

    float4 rA[4], rB[4];

    #pragma unroll
    for (int pass = 0; pass < 4; pass++) {
        int grow = rowBase + a_m0 + pass * 32;
        rA[pass] = (grow < M) ? *reinterpret_cast<const float4*>(A + (size_t)grow * K + a_k0)
                              : make_float4(0.f, 0.f, 0.f, 0.f);
        int k = b_k0 + pass * 8;
        rB[pass] = *reinterpret_cast<const float4*>(B + (size_t)k * N + colBase + b_n0);
    }

    int nIter = K / GBK;
    for (int it = 0; it < nIter; it++) {
        #pragma unroll
        for (int pass = 0; pass < 4; pass++) {
            int m = a_m0 + pass * 32;
            As[(a_k0 + 0) * ASTRIDE + m] = rA[pass].x;
            As[(a_k0 + 1) * ASTRIDE + m] = rA[pass].y;
            As[(a_k0 + 2) * ASTRIDE + m] = rA[pass].z;
            As[(a_k0 + 3) * ASTRIDE + m] = rA[pass].w;
            int k = b_k0 + pass * 8;
            *reinterpret_cast<float4*>(&Bs[k * BSTRIDE + b_n0]) = rB[pass];
        }
        __syncthreads();

        if (it + 1 < nIter) {
            int k0n = (it + 1) * GBK;
            #pragma unroll
            for (int pass = 0; pass < 4; pass++) {
                int grow = rowBase + a_m0 + pass * 32;
                rA[pass] = (grow < M) ? *reinterpret_cast<const float4*>(A + (size_t)grow * K + k0n + a_k0)
                                      : make_float4(0.f, 0.f, 0.f, 0.f);
                int k = b_k0 + pass * 8;
                rB[pass] = *reinterpret_cast<const float4*>(B + (size_t)(k0n + k) * N + colBase + b_n0);
            }
        }

        #pragma unroll
        for (int kk = 0; kk < GBK; kk += 8) {
            unsigned ah[2][4], al[2][4], bh[8][2], bl[8][2];
            #pragma unroll
            for (int mt = 0; mt < 2; mt++) {
                int mbase = wm + mt * 16;
                int r0 = (kk + tg) * ASTRIDE + mbase;
                int r1 = (kk + tg + 4) * ASTRIDE + mbase;
                hilo(As[r0 + g],     ah[mt][0], al[mt][0]);
                hilo(As[r0 + g + 8], ah[mt][1], al[mt][1]);
                hilo(As[r1 + g],     ah[mt][2], al[mt][2]);
                hilo(As[r1 + g + 8], ah[mt][3], al[mt][3]);
            }
            #pragma unroll
            for (int nt = 0; nt < 8; nt++) {
                int nbase = wn + nt * 8;
                hilo(Bs[(kk + tg)     * BSTRIDE + nbase + g], bh[nt][0], bl[nt][0]);
                hilo(Bs[(kk + tg + 4) * BSTRIDE + nbase + g], bh[nt][1], bl[nt][1]);
            }
            #pragma unroll
            for (int mt = 0; mt < 2; mt++)
                #pragma unroll
                for (int nt = 0; nt < 8; nt++) {
                    mma_tf32(acc[mt][nt], ah[mt], bh[nt]);   // hi*hi
                    mma_tf32(acc[mt][nt], ah[mt], bl[nt]);   // hi*lo
                    mma_tf32(acc[mt][nt], al[mt], bh[nt]);   // lo*hi
                }
        }
        __syncthreads();
    }

    #pragma unroll
    for (int mt = 0; mt < 2; mt++) {
        int r1 = rowBase + wm + mt * 16 + g;
        int r2 = r1 + 8;
        #pragma unroll
        for (int nt = 0; nt < 8; nt++) {
            int col = colBase + wn + nt * 8 + tg * 2;
            float bv0 = bias ? bias[col]     : 0.f;
            float bv1 = bias ? bias[col + 1] : 0.f;
            #pragma unroll
            for (int half = 0; half < 2; half++) {
                int r = half ? r2 : r1;
                if (r >= M) continue;
                float v0 = acc[mt][nt][half*2 + 0] + bv0;
                float v1 = acc[mt][nt][half*2 + 1] + bv1;
                if (ACT == 1) {
                    v0 = 0.5f * v0 * (1.0f + erff(v0 * 0.70710678118654752f));
                    v1 = 0.5f * v1 * (1.0f + erff(v1 * 0.70710678118654752f));
                }
                if (ACT == 2) { v0 = fmaxf(v0, 0.f); v1 = fmaxf(v1, 0.f); }
                size_t oi = (size_t)r * N + col;
                if (ACCUM) { C[oi] += v0; C[oi + 1] += v1; }
                else       { C[oi]  = v0; C[oi + 1]  = v1; }
            }
        }
    }
}

// ---------------- kernel 7: attention (K transposed in smem, conflict-free) ----------------
#define QT 8
#define SCP 208
#define TOKSP 201
#define ATTN_SMEM_FLOATS (HD*TOKSP + TOKS*HD + QT*HD + QT*SCP + 16)
__global__ void attn_kernel() {
    extern __shared__ float sm[];
    float* Kt = sm;
    float* Vs = Kt + HD*TOKSP;
    float* Qs = Vs + TOKS*HD;
    float* Sc = Qs + QT*HD;
    float* rowinv = Sc + QT*SCP;

    int bh = blockIdx.x;
    int b = bh / NHEAD, h = bh % NHEAD;
    int tid = threadIdx.x;
    const float* base = g_qkv + (size_t)b * TOKS * (3*Dm) + h * HD;

    for (int i = tid; i < TOKS*HD; i += 256) {
        int t = i >> 6, d = i & 63;
        Kt[d*TOKSP + t] = base[(size_t)t*(3*Dm) + Dm   + d];
        Vs[i]           = base[(size_t)t*(3*Dm) + 2*Dm + d];
    }
    __syncthreads();

    for (int q0 = 0; q0 < TOKS; q0 += QT) {
        int qn = min(QT, TOKS - q0);
        for (int i = tid; i < qn*HD; i += 256) {
            int qi = i >> 6, d = i & 63;
            Qs[qi*HD + d] = base[(size_t)(q0 + qi)*(3*Dm) + d];
        }
        __syncthreads();
        for (int qi = 0; qi < qn; qi++) {
            const float* qr = Qs + qi*HD;
            for (int j = tid; j < TOKS; j += 256) {
                float s = 0.f;
                #pragma unroll
                for (int d = 0; d < HD; d++) s += qr[d] * Kt[d*TOKSP + j];
                Sc[qi*SCP + j] = s * 0.125f;
            }
        }
        __syncthreads();
        {
            int w = tid >> 5, lane = tid & 31;
            if (w < qn) {
                float* row = Sc + w*SCP;
                float lm = -1e30f;
                for (int j = lane; j < TOKS; j += 32) lm = fmaxf(lm, row[j]);
                for (int o = 16; o; o >>= 1) lm = fmaxf(lm, __shfl_xor_sync(0xFFFFFFFFu, lm, o));
                float ls = 0.f;
                for (int j = lane; j < TOKS; j += 32) { float e = expf(row[j] - lm); row[j] = e; ls += e; }
                for (int o = 16; o; o >>= 1) ls += __shfl_xor_sync(0xFFFFFFFFu, ls, o);
                if (lane == 0) rowinv[w] = 1.f / ls;
            }
        }
        __syncthreads();
        for (int idx = tid; idx < qn*HD; idx += 256) {
            int qi = idx >> 6, d = idx & 63;
            const float* row = Sc + qi*SCP;
            float acc = 0.f;
            #pragma unroll 4
            for (int j = 0; j < TOKS; j++) acc += row[j] * Vs[j*HD + d];
            g_atto[((size_t)b*TOKS + q0 + qi)*Dm + h*HD + d] = acc * rowinv[qi];
        }
        __syncthreads();
    }
}

// ---------------- host ----------------
extern "C" void kernel_launch(void* const* d_in, const int* in_sizes, int n_in,
                              void* d_out, int out_size) {
    const float* x        = (const float*)d_in[0];
    const float* patch_w  = (const float*)d_in[1];
    const float* patch_b  = (const float*)d_in[2];
    const float* cls_tok  = (const float*)d_in[3];
    const float* pos_emb  = (const float*)d_in[4];
    const float* ln1_s    = (const float*)d_in[5];
    const float* ln1_b    = (const float*)d_in[6];
    const float* qkv_w    = (const float*)d_in[7];
    const float* qkv_b    = (const float*)d_in[8];
    const float* proj_w   = (const float*)d_in[9];
    const float* proj_b   = (const float*)d_in[10];
    const float* ln2_s    = (const float*)d_in[11];
    const float* ln2_b    = (const float*)d_in[12];
    const float* mlp1_w   = (const float*)d_in[13];
    const float* mlp1_b   = (const float*)d_in[14];
    const float* mlp2_w   = (const float*)d_in[15];
    const float* mlp2_b   = (const float*)d_in[16];
    const float* lnf_s    = (const float*)d_in[17];
    const float* lnf_b    = (const float*)d_in[18];
    const float* head_w   = (const float*)d_in[19];
    const float* head_b   = (const float*)d_in[20];
    const float* fc1_w    = (const float*)d_in[21];
    const float* fc1_b    = (const float*)d_in[22];
    const float* fc2_w    = (const float*)d_in[23];
    const float* fc2_b    = (const float*)d_in[24];
    float* out = (float*)d_out;

    float *p_patches, *p_ptok, *p_tok, *p_h, *p_mlp, *p_atto, *p_cls, *p_feat, *p_fc1, *p_qkv;
    cudaGetSymbolAddress((void**)&p_patches, g_patches);
    cudaGetSymbolAddress((void**)&p_ptok,    g_ptok);
    cudaGetSymbolAddress((void**)&p_tok,     g_tok);
    cudaGetSymbolAddress((void**)&p_h,       g_h);
    cudaGetSymbolAddress((void**)&p_mlp,     g_mlp);
    cudaGetSymbolAddress((void**)&p_atto,    g_atto);
    cudaGetSymbolAddress((void**)&p_cls,     g_cls);
    cudaGetSymbolAddress((void**)&p_feat,    g_feat);
    cudaGetSymbolAddress((void**)&p_fc1,     g_fc1);
    cudaGetSymbolAddress((void**)&p_qkv,     g_qkv);

    const int ATTN_SMEM = ATTN_SMEM_FLOATS * (int)sizeof(float);
    cudaFuncSetAttribute(attn_kernel, cudaFuncAttributeMaxDynamicSharedMemorySize, ATTN_SMEM);

    float* target_out = (out_size >= Nb*NFRAG*2*2) ? (out + Nb*NFRAG*2) : nullptr;
    rng_kernel<<<1, 512>>>(target_out);

    augment_kernel<<<Nb*NFRAG*3, 256>>>(x);

    {
        int total = Nb*NPT*Dm;
        patchify_kernel<<<(total + 255)/256, 256>>>();
    }

    auto g64  = [](int M, int N) { return dim3((unsigned)((N + 63)/64),  (unsigned)((M + 63)/64)); };
    auto g128 = [](int M, int N) { return dim3((unsigned)(N/128), (unsigned)((M + 127)/128)); };

    gemm_tf32_kernel<0><<<g128(Nb*NPT, Dm), 256>>>(p_patches, patch_w, patch_b, p_ptok, Nb*NPT, Dm, Dm, 0);
    {
        int total = Nb*TOKS*Dm;
        assemble_kernel<<<(total + 255)/256, 256>>>(cls_tok, pos_emb);
    }

    for (int l = 0; l < NL; l++) {
        ln_kernel<<<ROWS, 256>>>(p_tok, Dm, ln1_s + (size_t)l*Dm, ln1_b + (size_t)l*Dm, p_h, Dm);
        gemm_tf32_kernel<0><<<g128(ROWS, 3*Dm), 256>>>(p_h, qkv_w + (size_t)l*Dm*3*Dm, qkv_b + (size_t)l*3*Dm,
                                                       p_qkv, ROWS, 3*Dm, Dm, 0);
        attn_kernel<<<Nb*NHEAD, 256, ATTN_SMEM>>>();
        gemm_tf32_kernel<0><<<g128(ROWS, Dm), 256>>>(p_atto, proj_w + (size_t)l*Dm*Dm, proj_b + (size_t)l*Dm,
                                                     p_tok, ROWS, Dm, Dm, 1);
        ln_kernel<<<ROWS, 256>>>(p_tok, Dm, ln2_s + (size_t)l*Dm, ln2_b + (size_t)l*Dm, p_h, Dm);
        gemm_tf32_kernel<1><<<g128(ROWS, MLPD), 256>>>(p_h, mlp1_w + (size_t)l*Dm*MLPD, mlp1_b + (size_t)l*MLPD,
                                                       p_mlp, ROWS, MLPD, Dm, 0);
        gemm_tf32_kernel<0><<<g128(ROWS, Dm), 256>>>(p_mlp, mlp2_w + (size_t)l*MLPD*Dm, mlp2_b + (size_t)l*Dm,
                                                     p_tok, ROWS, Dm, MLPD, 1);
    }

    ln_kernel<<<Nb, 256>>>(p_tok, (long long)TOKS*Dm, lnf_s, lnf_b, p_cls, Dm);
    sgemm_kernel<0><<<g64(Nb, NCLS), 256>>>(p_cls, head_w, head_b, p_feat, Nb, NCLS, Dm, 0);
    sgemm_kernel<2><<<g64(Nb, NCLS), 256>>>(p_feat, fc1_w, fc1_b, p_fc1, Nb, NCLS, NCLS, 0);
    sgemm_kernel<0><<<g64(Nb, NFRAG*2), 256>>>(p_fc1, fc2_w, fc2_b, out, Nb, NFRAG*2, NCLS, 0);
}

// round 14
// speedup vs baseline: 2.7072x; 1.0608x over previous
#include <cuda_runtime.h>
#include <math.h>

// ---------------- problem constants ----------------
#define Nb    32
#define Pfr   75
#define NGRID 3
#define NFRAG 9
#define CROPS 64
#define PUZ   225
#define IMGS  224
#define PATCH 16
#define NPT   196
#define Dm    768
#define NHEAD 12
#define HD    64
#define NL    12
#define MLPD  3072
#define NCLS  1000
#define TOKS  197
#define ROWS  (Nb*TOKS)   // 6304

// ---------------- scratch (static device globals; no allocation) ----------------
__device__ float g_img[Nb*3*PUZ*PUZ];
__device__ float g_patches[(size_t)Nb*NPT*Dm];
__device__ float g_ptok[(size_t)Nb*NPT*Dm];
__device__ float g_tok[(size_t)ROWS*Dm];
__device__ float g_h[(size_t)ROWS*Dm];
__device__ float g_qkv[(size_t)ROWS*3*Dm];
__device__ float g_atto[(size_t)ROWS*Dm];
__device__ float g_mlp[(size_t)ROWS*MLPD];
__device__ float g_cls[Nb*Dm];
__device__ float g_feat[Nb*NCLS];
__device__ float g_fc1[Nb*NCLS];
__device__ int   g_shuffle[Nb*NFRAG];
__device__ int   g_offs[Nb*NFRAG*2];
__device__ int   g_jitt[Nb*NFRAG*3];

// ---------------- threefry2x32 (KAT-verified core) ----------------
__device__ __forceinline__ void threefry(unsigned k0, unsigned k1, unsigned &x0, unsigned &x1) {
    unsigned ks0 = k0, ks1 = k1, ks2 = k0 ^ k1 ^ 0x1BD11BDAu;
    x0 += ks0; x1 += ks1;
#define TFRND(r) { x0 += x1; x1 = (x1 << (r)) | (x1 >> (32 - (r))); x1 ^= x0; }
    TFRND(13) TFRND(15) TFRND(26) TFRND(6);  x0 += ks1; x1 += ks2 + 1u;
    TFRND(17) TFRND(29) TFRND(16) TFRND(24); x0 += ks2; x1 += ks0 + 2u;
    TFRND(13) TFRND(15) TFRND(26) TFRND(6);  x0 += ks0; x1 += ks1 + 3u;
    TFRND(17) TFRND(29) TFRND(16) TFRND(24); x0 += ks1; x1 += ks2 + 4u;
    TFRND(13) TFRND(15) TFRND(26) TFRND(6);  x0 += ks2; x1 += ks0 + 5u;
#undef TFRND
}

__device__ __forceinline__ unsigned rb32_part(unsigned k0, unsigned k1, unsigned i) {
    unsigned x0 = 0u, x1 = i;
    threefry(k0, k1, x0, x1);
    return x0 ^ x1;
}

__device__ __forceinline__ void split_key(unsigned k0, unsigned k1, unsigned t,
                                          unsigned &o0, unsigned &o1) {
    unsigned x0 = 0u, x1 = t;
    threefry(k0, k1, x0, x1);
    o0 = x0; o1 = x1;
}

// ---------------- kernel 1: RNG setup + target output ----------------
__global__ void rng_kernel(float* target_out) {
    __shared__ unsigned keys[14];
    __shared__ float noise[Nb*NFRAG];
    int tid = threadIdx.x;

    if (tid == 0) {
        for (int t = 0; t < 3; t++)
            split_key(0u, 42u, (unsigned)t, keys[2*t], keys[2*t+1]);
        split_key(keys[2], keys[3], 0u, keys[6],  keys[7]);
        split_key(keys[2], keys[3], 1u, keys[8],  keys[9]);
        split_key(keys[4], keys[5], 0u, keys[10], keys[11]);
        split_key(keys[4], keys[5], 1u, keys[12], keys[13]);
    }
    __syncthreads();

    if (tid < Nb*NFRAG) {
        unsigned bits = rb32_part(keys[0], keys[1], (unsigned)tid);
        noise[tid] = __uint_as_float((bits >> 9) | 0x3F800000u) - 1.0f;
    }
    __syncthreads();

    if (tid < Nb) {
        int ids[NFRAG];
        unsigned used = 0;
        for (int r = 0; r < NFRAG; r++) {
            int best = -1;
            for (int j = 0; j < NFRAG; j++) {
                if (used & (1u << j)) continue;
                if (best < 0 || noise[tid*NFRAG + j] < noise[tid*NFRAG + best]) best = j;
            }
            ids[r] = best; used |= (1u << best);
        }
        int rest[NFRAG];
        for (int r = 0; r < NFRAG; r++) { g_shuffle[tid*NFRAG + r] = ids[r]; rest[ids[r]] = r; }
        if (target_out) {
            for (int f = 0; f < NFRAG; f++) {
                target_out[(tid*NFRAG + f)*2 + 0] = (float)(rest[f] / 3);
                target_out[(tid*NFRAG + f)*2 + 1] = (float)(rest[f] % 3);
            }
        }
    }

    for (int i = tid; i < Nb*NFRAG*2; i += blockDim.x) {
        unsigned hi = rb32_part(keys[6], keys[7], (unsigned)i);
        unsigned lo = rb32_part(keys[8], keys[9], (unsigned)i);
        unsigned v = (((hi % 12u) * 4u) + (lo % 12u)) % 12u;
        g_offs[i] = (int)v;
    }
    for (int i = tid; i < Nb*NFRAG*3; i += blockDim.x) {
        unsigned hi = rb32_part(keys[10], keys[11], (unsigned)i);
        unsigned lo = rb32_part(keys[12], keys[13], (unsigned)i);
        unsigned v = ((hi % 5u) + (lo % 5u)) % 5u;
        g_jitt[i] = (int)v - 2;
    }
}

// ---------------- block reductions (blockDim == 256) ----------------
__device__ __forceinline__ float bsum256(float v, float* red8) {
    for (int o = 16; o; o >>= 1) v += __shfl_xor_sync(0xFFFFFFFFu, v, o);
    if ((threadIdx.x & 31) == 0) red8[threadIdx.x >> 5] = v;
    __syncthreads();
    float r = red8[0]+red8[1]+red8[2]+red8[3]+red8[4]+red8[5]+red8[6]+red8[7];
    __syncthreads();
    return r;
}

// ---------------- kernel 2: augment ----------------
__global__ void augment_kernel(const float* __restrict__ x) {
    __shared__ float buf[Pfr*Pfr];
    __shared__ float red8[8];
    int bfc = blockIdx.x;
    int c = bfc % 3;
    int bf = bfc / 3;
    int b = bf / NFRAG, f = bf % NFRAG;

    int src = g_shuffle[bf];
    int sr = (src / 3) * Pfr + g_offs[2*bf + 0];
    int sc = (src % 3) * Pfr + g_offs[2*bf + 1];
    float jitv = (float)g_jitt[bf*3 + c];
    const float* xp = x + ((size_t)b*3 + c) * PUZ * PUZ;

    const float sf = 64.0f / 75.0f;
    float lsum = 0.f;
    for (int idx = threadIdx.x; idx < Pfr*Pfr; idx += 256) {
        int i = idx / Pfr, j = idx % Pfr;
        float fy = (i + 0.5f) * sf - 0.5f;
        float fx = (j + 0.5f) * sf - 0.5f;
        int   y0 = (int)floorf(fy); float dy = fy - (float)y0;
        int   x0 = (int)floorf(fx); float dx = fx - (float)x0;
        int y0c = max(0, min(63, y0)),   y1c = max(0, min(63, y0 + 1));
        int x0c = max(0, min(63, x0)),   x1c = max(0, min(63, x0 + 1));
        const float* r0 = xp + (size_t)(sr + y0c) * PUZ + sc;
        const float* r1 = xp + (size_t)(sr + y1c) * PUZ + sc;
        float v = (1.f-dy)*((1.f-dx)*r0[x0c] + dx*r0[x1c])
                +       dy*((1.f-dx)*r1[x0c] + dx*r1[x1c]);
        v = v + jitv;
        v = fminf(fmaxf(v, 0.f), 255.f);
        buf[idx] = v;
        lsum += v;
    }
    float m = bsum256(lsum, red8) * (1.0f / (Pfr*Pfr));
    float lss = 0.f;
    for (int idx = threadIdx.x; idx < Pfr*Pfr; idx += 256) {
        float d = buf[idx] - m;
        lss += d * d;
    }
    float ss = bsum256(lss, red8);
    float s = sqrtf(ss / (float)(Pfr*Pfr - 1));
    if (s == 0.f) s = 1.f;

    int gi = f / 3, gj = f % 3;
    float* op = g_img + ((size_t)b*3 + c) * PUZ * PUZ + (size_t)gi*Pfr*PUZ + gj*Pfr;
    for (int idx = threadIdx.x; idx < Pfr*Pfr; idx += 256) {
        op[(idx / Pfr) * PUZ + (idx % Pfr)] = (buf[idx] - m) / s;
    }
}

// ---------------- kernel 3: patchify ----------------
__global__ void patchify_kernel() {
    int idx = blockIdx.x * blockDim.x + threadIdx.x;
    if (idx >= Nb*NPT*Dm) return;
    int k = idx % Dm;
    int p = (idx / Dm) % NPT;
    int b = idx / (Dm * NPT);
    int c = k >> 8, u = (k >> 4) & 15, v = k & 15;
    int pi = p / 14, pj = p % 14;
    g_patches[idx] = g_img[(((size_t)b*3 + c) * PUZ + (pi*16 + u)) * PUZ + (pj*16 + v)];
}

// ---------------- kernel 4: token assemble ----------------
__global__ void assemble_kernel(const float* __restrict__ clstok, const float* __restrict__ pos) {
    int idx = blockIdx.x * blockDim.x + threadIdx.x;
    if (idx >= Nb*TOKS*Dm) return;
    int d = idx % Dm;
    int t = (idx / Dm) % TOKS;
    int b = idx / (Dm * TOKS);
    float v = (t == 0) ? clstok[d] : g_ptok[((size_t)b*NPT + (t-1))*Dm + d];
    g_tok[idx] = v + pos[t*Dm + d];
}

// ---------------- kernel 5: layernorm ----------------
__global__ void ln_kernel(const float* __restrict__ x, long long sx,
                          const float* __restrict__ s, const float* __restrict__ b,
                          float* __restrict__ y, long long sy) {
    __shared__ float red8[8];
    const float* xr = x + (long long)blockIdx.x * sx;
    float* yr = y + (long long)blockIdx.x * sy;
    int t = threadIdx.x;
    float v0 = xr[t], v1 = xr[t+256], v2 = xr[t+512];
    float m = bsum256(v0+v1+v2, red8) * (1.0f/768.0f);
    float d0 = v0-m, d1 = v1-m, d2 = v2-m;
    float var = bsum256(d0*d0 + d1*d1 + d2*d2, red8) * (1.0f/768.0f);
    float inv = rsqrtf(var + 1e-6f);
    yr[t]     = d0*inv*s[t]     + b[t];
    yr[t+256] = d1*inv*s[t+256] + b[t+256];
    yr[t+512] = d2*inv*s[t+512] + b[t+512];
}

// ---------------- kernel 6a: small fp32 SGEMM (head only) ----------------
template<int ACT>
__global__ void sgemm_kernel(const float* __restrict__ A, const float* __restrict__ B,
                             const float* __restrict__ bias, float* __restrict__ C,
                             int M, int N, int K, int ACCUM) {
    __shared__ float As[16][64];
    __shared__ float Bs[16][64];
    int tid = threadIdx.x;
    int tx = tid & 15, ty = tid >> 4;
    int blockRow = blockIdx.y * 64;
    int blockCol = blockIdx.x * 64;
    float acc[4][4] = {};

    for (int k0 = 0; k0 < K; k0 += 16) {
        #pragma unroll
        for (int t = tid; t < 64*16; t += 256) {
            int m  = t >> 4, kk  = t & 15;
            int gr = blockRow + m, gc = k0 + kk;
            As[kk][m] = (gr < M && gc < K) ? A[(size_t)gr*K + gc] : 0.f;
            int kk2 = t >> 6, nn = t & 63;
            int gr2 = k0 + kk2, gc2 = blockCol + nn;
            Bs[kk2][nn] = (gr2 < K && gc2 < N) ? B[(size_t)gr2*N + gc2] : 0.f;
        }
        __syncthreads();
        #pragma unroll
        for (int kk = 0; kk < 16; kk++) {
            float a[4], bb[4];
            #pragma unroll
            for (int i = 0; i < 4; i++) a[i]  = As[kk][ty*4 + i];
            #pragma unroll
            for (int j = 0; j < 4; j++) bb[j] = Bs[kk][tx*4 + j];
            #pragma unroll
            for (int i = 0; i < 4; i++)
                #pragma unroll
                for (int j = 0; j < 4; j++)
                    acc[i][j] += a[i] * bb[j];
        }
        __syncthreads();
    }

    #pragma unroll
    for (int i = 0; i < 4; i++) {
        int r = blockRow + ty*4 + i;
        if (r >= M) continue;
        #pragma unroll
        for (int j = 0; j < 4; j++) {
            int cc = blockCol + tx*4 + j;
            if (cc >= N) continue;
            float v = acc[i][j] + (bias ? bias[cc] : 0.f);
            if (ACT == 1) v = 0.5f * v * (1.0f + erff(v * 0.70710678118654752f));
            if (ACT == 2) v = fmaxf(v, 0.f);
            size_t oi = (size_t)r * N + cc;
            if (ACCUM) C[oi] += v; else C[oi] = v;
        }
    }
}

// ---------------- kernel 6b: 3xTF32 GEMM, cp.async double-buffered, occ 2 ----------------
// C[M,N] = act(A[M,K] @ B[K,N] + bias) [+= C]; N%128==0, K%32==0, M arbitrary.
#define GBM 128
#define GBN 128
#define GBK 32
#define ASTR 36        // A smem m-major: As[m][k], 36%32==4 -> frag reads conflict-free
#define BSTR 132       // B smem k-major: Bs[k][n], 132%32==4 -> frag reads conflict-free
#define ABUF (GBM*ASTR)   // 4608 floats
#define BBUF (GBK*BSTR)   // 4224 floats
#define GEMM_SMEM_BYTES ((2*ABUF + 2*BBUF) * 4)   // 70656 B

__device__ __forceinline__ unsigned f2tf32(float f) {
    unsigned r;
    asm("cvt.rna.tf32.f32 %0, %1;" : "=r"(r) : "f"(f));
    return r;
}

__device__ __forceinline__ void mma_tf32(float* c, const unsigned* a, const unsigned* b) {
    asm volatile(
        "mma.sync.aligned.m16n8k8.row.col.f32.tf32.tf32.f32 "
        "{%0,%1,%2,%3}, {%4,%5,%6,%7}, {%8,%9}, {%0,%1,%2,%3};"
        : "+f"(c[0]), "+f"(c[1]), "+f"(c[2]), "+f"(c[3])
        : "r"(a[0]), "r"(a[1]), "r"(a[2]), "r"(a[3]), "r"(b[0]), "r"(b[1]));
}

__device__ __forceinline__ void hilo(float v, unsigned &h, unsigned &l) {
    h = f2tf32(v);
    l = __float_as_uint(v - __uint_as_float(h));
}

__device__ __forceinline__ void cp16(unsigned saddr, const void* g, unsigned nbytes) {
    asm volatile("cp.async.ca.shared.global [%0], [%1], 16, %2;\n"
                 :: "r"(saddr), "l"(g), "r"(nbytes));
}

template<int ACT>
__global__ __launch_bounds__(256, 2)
void gemm_tf32_kernel(const float* __restrict__ A, const float* __restrict__ B,
                      const float* __restrict__ bias, float* __restrict__ C,
                      int M, int N, int K, int ACCUM) {
    extern __shared__ float gsm[];
    float* As = gsm;              // [2][GBM][ASTR]
    float* Bs = gsm + 2*ABUF;     // [2][GBK][BSTR]
    unsigned asBase = (unsigned)__cvta_generic_to_shared(As);
    unsigned bsBase = (unsigned)__cvta_generic_to_shared(Bs);

    int tid  = threadIdx.x;
    int lane = tid & 31;
    int warp = tid >> 5;
    int g  = lane >> 2;
    int tg = lane & 3;
    int wm = (warp & 3) * 32;
    int wn = (warp >> 2) * 64;

    int rowBase = blockIdx.y * GBM;
    int colBase = blockIdx.x * GBN;

    // copy mappings
    int am  = tid >> 1;                 // A row 0..127
    int ah4 = (tid & 1) * 16;           // A float offset 0/16
    int bk  = tid >> 3;                 // B row 0..31
    int bp  = (tid & 7) * 16;           // B float offset

    const float* gAr = A + (size_t)(rowBase + am) * K + ah4;
    unsigned     aOK = (rowBase + am < M) ? 16u : 0u;
    const float* gBr = B + (size_t)bk * N + colBase + bp;

    float acc[2][8][4];
    #pragma unroll
    for (int mt = 0; mt < 2; mt++)
        #pragma unroll
        for (int nt = 0; nt < 8; nt++)
            #pragma unroll
            for (int i = 0; i < 4; i++) acc[mt][nt][i] = 0.f;

    int nIter = K / GBK;

    // prologue: load tile 0 into buffer 0
    {
        unsigned sa = asBase + (unsigned)((am*ASTR + ah4) * 4);
        unsigned sb = bsBase + (unsigned)((bk*BSTR + bp) * 4);
        #pragma unroll
        for (int j = 0; j < 4; j++) cp16(sa + 16*j, gAr + 4*j, aOK);
        #pragma unroll
        for (int j = 0; j < 4; j++) cp16(sb + 16*j, gBr + 4*j, 16u);
        asm volatile("cp.async.commit_group;\n" ::);
    }

    for (int it = 0; it < nIter; it++) {
        int buf = it & 1;
        if (it + 1 < nIter) {
            int nb = (it + 1) & 1;
            int k0n = (it + 1) * GBK;
            unsigned sa = asBase + (unsigned)((nb*ABUF + am*ASTR + ah4) * 4);
            unsigned sb = bsBase + (unsigned)((nb*BBUF + bk*BSTR + bp) * 4);
            const float* ga = gAr + k0n;
            const float* gb = gBr + (size_t)k0n * N;
            #pragma unroll
            for (int j = 0; j < 4; j++) cp16(sa + 16*j, ga + 4*j, aOK);
            #pragma unroll
            for (int j = 0; j < 4; j++) cp16(sb + 16*j, gb + 4*j, 16u);
            asm volatile("cp.async.commit_group;\n" ::);
            asm volatile("cp.async.wait_group 1;\n" ::);
        } else {
            asm volatile("cp.async.wait_group 0;\n" ::);
        }
        __syncthreads();

        const float* Ab = As + buf*ABUF;
        const float* Bb = Bs + buf*BBUF;

        #pragma unroll
        for (int kk = 0; kk < GBK; kk += 8) {
            unsigned ah[2][4], al[2][4], bh[8][2], bl[8][2];
            #pragma unroll
            for (int mt = 0; mt < 2; mt++) {
                int mb = wm + mt * 16;
                hilo(Ab[(mb + g)     * ASTR + kk + tg],     ah[mt][0], al[mt][0]);
                hilo(Ab[(mb + g + 8) * ASTR + kk + tg],     ah[mt][1], al[mt][1]);
                hilo(Ab[(mb + g)     * ASTR + kk + tg + 4], ah[mt][2], al[mt][2]);
                hilo(Ab[(mb + g + 8) * ASTR + kk + tg + 4], ah[mt][3], al[mt][3]);
            }
            #pragma unroll
            for (int nt = 0; nt < 8; nt++) {
                int nb2 = wn + nt * 8;
                hilo(Bb[(kk + tg)     * BSTR + nb2 + g], bh[nt][0], bl[nt][0]);
                hilo(Bb[(kk + tg + 4) * BSTR + nb2 + g], bh[nt][1], bl[nt][1]);
            }
            #pragma unroll
            for (int mt = 0; mt < 2; mt++)
                #pragma unroll
                for (int nt = 0; nt < 8; nt++) {
                    mma_tf32(acc[mt][nt], ah[mt], bh[nt]);
                    mma_tf32(acc[mt][nt], ah[mt], bl[nt]);
                    mma_tf32(acc[mt][nt], al[mt], bh[nt]);
                }
        }
        __syncthreads();
    }

    // epilogue
    #pragma unroll
    for (int mt = 0; mt < 2; mt++) {
        int r1 = rowBase + wm + mt * 16 + g;
        int r2 = r1 + 8;
        #pragma unroll
        for (int nt = 0; nt < 8; nt++) {
            int col = colBase + wn + nt * 8 + tg * 2;
            float bv0 = bias ? bias[col]     : 0.f;
            float bv1 = bias ? bias[col + 1] : 0.f;
            #pragma unroll
            for (int half = 0; half < 2; half++) {
                int r = half ? r2 : r1;
                if (r >= M) continue;
                float v0 = acc[mt][nt][half*2 + 0] + bv0;
                float v1 = acc[mt][nt][half*2 + 1] + bv1;
                if (ACT == 1) {
                    v0 = 0.5f * v0 * (1.0f + erff(v0 * 0.70710678118654752f));
                    v1 = 0.5f * v1 * (1.0f + erff(v1 * 0.70710678118654752f));
                }
                if (ACT == 2) { v0 = fmaxf(v0, 0.f); v1 = fmaxf(v1, 0.f); }
                size_t oi = (size_t)r * N + col;
                if (ACCUM) { C[oi] += v0; C[oi + 1] += v1; }
                else       { C[oi]  = v0; C[oi + 1]  = v1; }
            }
        }
    }
}

// ---------------- kernel 7: attention (K transposed in smem, conflict-free) ----------------
#define QT 8
#define SCP 208
#define TOKSP 201
#define ATTN_SMEM_FLOATS (HD*TOKSP + TOKS*HD + QT*HD + QT*SCP + 16)
__global__ void attn_kernel() {
    extern __shared__ float sm[];
    float* Kt = sm;
    float* Vs = Kt + HD*TOKSP;
    float* Qs = Vs + TOKS*HD;
    float* Sc = Qs + QT*HD;
    float* rowinv = Sc + QT*SCP;

    int bh = blockIdx.x;
    int b = bh / NHEAD, h = bh % NHEAD;
    int tid = threadIdx.x;
    const float* base = g_qkv + (size_t)b * TOKS * (3*Dm) + h * HD;

    for (int i = tid; i < TOKS*HD; i += 256) {
        int t = i >> 6, d = i & 63;
        Kt[d*TOKSP + t] = base[(size_t)t*(3*Dm) + Dm   + d];
        Vs[i]           = base[(size_t)t*(3*Dm) + 2*Dm + d];
    }
    __syncthreads();

    for (int q0 = 0; q0 < TOKS; q0 += QT) {
        int qn = min(QT, TOKS - q0);
        for (int i = tid; i < qn*HD; i += 256) {
            int qi = i >> 6, d = i & 63;
            Qs[qi*HD + d] = base[(size_t)(q0 + qi)*(3*Dm) + d];
        }
        __syncthreads();
        for (int qi = 0; qi < qn; qi++) {
            const float* qr = Qs + qi*HD;
            for (int j = tid; j < TOKS; j += 256) {
                float s = 0.f;
                #pragma unroll
                for (int d = 0; d < HD; d++) s += qr[d] * Kt[d*TOKSP + j];
                Sc[qi*SCP + j] = s * 0.125f;
            }
        }
        __syncthreads();
        {
            int w = tid >> 5, lane = tid & 31;
            if (w < qn) {
                float* row = Sc + w*SCP;
                float lm = -1e30f;
                for (int j = lane; j < TOKS; j += 32) lm = fmaxf(lm, row[j]);
                for (int o = 16; o; o >>= 1) lm = fmaxf(lm, __shfl_xor_sync(0xFFFFFFFFu, lm, o));
                float ls = 0.f;
                for (int j = lane; j < TOKS; j += 32) { float e = expf(row[j] - lm); row[j] = e; ls += e; }
                for (int o = 16; o; o >>= 1) ls += __shfl_xor_sync(0xFFFFFFFFu, ls, o);
                if (lane == 0) rowinv[w] = 1.f / ls;
            }
        }
        __syncthreads();
        for (int idx = tid; idx < qn*HD; idx += 256) {
            int qi = idx >> 6, d = idx & 63;
            const float* row = Sc + qi*SCP;
            float acc = 0.f;
            #pragma unroll 4
            for (int j = 0; j < TOKS; j++) acc += row[j] * Vs[j*HD + d];
            g_atto[((size_t)b*TOKS + q0 + qi)*Dm + h*HD + d] = acc * rowinv[qi];
        }
        __syncthreads();
    }
}

// ---------------- host ----------------
extern "C" void kernel_launch(void* const* d_in, const int* in_sizes, int n_in,
                              void* d_out, int out_size) {
    const float* x        = (const float*)d_in[0];
    const float* patch_w  = (const float*)d_in[1];
    const float* patch_b  = (const float*)d_in[2];
    const float* cls_tok  = (const float*)d_in[3];
    const float* pos_emb  = (const float*)d_in[4];
    const float* ln1_s    = (const float*)d_in[5];
    const float* ln1_b    = (const float*)d_in[6];
    const float* qkv_w    = (const float*)d_in[7];
    const float* qkv_b    = (const float*)d_in[8];
    const float* proj_w   = (const float*)d_in[9];
    const float* proj_b   = (const float*)d_in[10];
    const float* ln2_s    = (const float*)d_in[11];
    const float* ln2_b    = (const float*)d_in[12];
    const float* mlp1_w   = (const float*)d_in[13];
    const float* mlp1_b   = (const float*)d_in[14];
    const float* mlp2_w   = (const float*)d_in[15];
    const float* mlp2_b   = (const float*)d_in[16];
    const float* lnf_s    = (const float*)d_in[17];
    const float* lnf_b    = (const float*)d_in[18];
    const float* head_w   = (const float*)d_in[19];
    const float* head_b   = (const float*)d_in[20];
    const float* fc1_w    = (const float*)d_in[21];
    const float* fc1_b    = (const float*)d_in[22];
    const float* fc2_w    = (const float*)d_in[23];
    const float* fc2_b    = (const float*)d_in[24];
    float* out = (float*)d_out;

    float *p_patches, *p_ptok, *p_tok, *p_h, *p_mlp, *p_atto, *p_cls, *p_feat, *p_fc1, *p_qkv;
    cudaGetSymbolAddress((void**)&p_patches, g_patches);
    cudaGetSymbolAddress((void**)&p_ptok,    g_ptok);
    cudaGetSymbolAddress((void**)&p_tok,     g_tok);
    cudaGetSymbolAddress((void**)&p_h,       g_h);
    cudaGetSymbolAddress((void**)&p_mlp,     g_mlp);
    cudaGetSymbolAddress((void**)&p_atto,    g_atto);
    cudaGetSymbolAddress((void**)&p_cls,     g_cls);
    cudaGetSymbolAddress((void**)&p_feat,    g_feat);
    cudaGetSymbolAddress((void**)&p_fc1,     g_fc1);
    cudaGetSymbolAddress((void**)&p_qkv,     g_qkv);

    const int ATTN_SMEM = ATTN_SMEM_FLOATS * (int)sizeof(float);
    cudaFuncSetAttribute(attn_kernel, cudaFuncAttributeMaxDynamicSharedMemorySize, ATTN_SMEM);
    cudaFuncSetAttribute(gemm_tf32_kernel<0>, cudaFuncAttributeMaxDynamicSharedMemorySize, GEMM_SMEM_BYTES);
    cudaFuncSetAttribute(gemm_tf32_kernel<1>, cudaFuncAttributeMaxDynamicSharedMemorySize, GEMM_SMEM_BYTES);

    float* target_out = (out_size >= Nb*NFRAG*2*2) ? (out + Nb*NFRAG*2) : nullptr;
    rng_kernel<<<1, 512>>>(target_out);

    augment_kernel<<<Nb*NFRAG*3, 256>>>(x);

    {
        int total = Nb*NPT*Dm;
        patchify_kernel<<<(total + 255)/256, 256>>>();
    }

    auto g64  = [](int M, int N) { return dim3((unsigned)((N + 63)/64),  (unsigned)((M + 63)/64)); };
    auto g128 = [](int M, int N) { return dim3((unsigned)(N/128), (unsigned)((M + 127)/128)); };

    gemm_tf32_kernel<0><<<g128(Nb*NPT, Dm), 256, GEMM_SMEM_BYTES>>>(p_patches, patch_w, patch_b, p_ptok, Nb*NPT, Dm, Dm, 0);
    {
        int total = Nb*TOKS*Dm;
        assemble_kernel<<<(total + 255)/256, 256>>>(cls_tok, pos_emb);
    }

    for (int l = 0; l < NL; l++) {
        ln_kernel<<<ROWS, 256>>>(p_tok, Dm, ln1_s + (size_t)l*Dm, ln1_b + (size_t)l*Dm, p_h, Dm);
        gemm_tf32_kernel<0><<<g128(ROWS, 3*Dm), 256, GEMM_SMEM_BYTES>>>(p_h, qkv_w + (size_t)l*Dm*3*Dm, qkv_b + (size_t)l*3*Dm,
                                                       p_qkv, ROWS, 3*Dm, Dm, 0);
        attn_kernel<<<Nb*NHEAD, 256, ATTN_SMEM>>>();
        gemm_tf32_kernel<0><<<g128(ROWS, Dm), 256, GEMM_SMEM_BYTES>>>(p_atto, proj_w + (size_t)l*Dm*Dm, proj_b + (size_t)l*Dm,
                                                     p_tok, ROWS, Dm, Dm, 1);
        ln_kernel<<<ROWS, 256>>>(p_tok, Dm, ln2_s + (size_t)l*Dm, ln2_b + (size_t)l*Dm, p_h, Dm);
        gemm_tf32_kernel<1><<<g128(ROWS, MLPD), 256, GEMM_SMEM_BYTES>>>(p_h, mlp1_w + (size_t)l*Dm*MLPD, mlp1_b + (size_t)l*MLPD,
                                                       p_mlp, ROWS, MLPD, Dm, 0);
        gemm_tf32_kernel<0><<<g128(ROWS, Dm), 256, GEMM_SMEM_BYTES>>>(p_mlp, mlp2_w + (size_t)l*MLPD*Dm, mlp2_b + (size_t)l*Dm,
                                                     p_tok, ROWS, Dm, MLPD, 1);
    }

    ln_kernel<<<Nb, 256>>>(p_tok, (long long)TOKS*Dm, lnf_s, lnf_b, p_cls, Dm);
    sgemm_kernel<0><<<g64(Nb, NCLS), 256>>>(p_cls, head_w, head_b, p_feat, Nb, NCLS, Dm, 0);
    sgemm_kernel<2><<<g64(Nb, NCLS), 256>>>(p_feat, fc1_w, fc1_b, p_fc1, Nb, NCLS, NCLS, 0);
    sgemm_kernel<0><<<g64(Nb, NFRAG*2), 256>>>(p_fc1, fc2_w, fc2_b, out, Nb, NFRAG*2, NCLS, 0);
}

// round 15
// speedup vs baseline: 3.2800x; 1.2116x over previous
#include <cuda_runtime.h>
#include <math.h>

// ---------------- problem constants ----------------
#define Nb    32
#define Pfr   75
#define NGRID 3
#define NFRAG 9
#define CROPS 64
#define PUZ   225
#define IMGS  224
#define PATCH 16
#define NPT   196
#define Dm    768
#define NHEAD 12
#define HD    64
#define NL    12
#define MLPD  3072
#define NCLS  1000
#define TOKS  197
#define ROWS  (Nb*TOKS)   // 6304

// ---------------- scratch (static device globals; no allocation) ----------------
__device__ float g_img[Nb*3*PUZ*PUZ];
__device__ float g_patches[(size_t)Nb*NPT*Dm];
__device__ float g_ptok[(size_t)Nb*NPT*Dm];
__device__ float g_tok[(size_t)ROWS*Dm];
__device__ float g_h[(size_t)ROWS*Dm];
__device__ float g_qkv[(size_t)ROWS*3*Dm];
__device__ float g_atto[(size_t)ROWS*Dm];
__device__ float g_mlp[(size_t)ROWS*MLPD];
__device__ float g_cls[Nb*Dm];
__device__ float g_feat[Nb*NCLS];
__device__ float g_fc1[Nb*NCLS];
__device__ int   g_shuffle[Nb*NFRAG];
__device__ int   g_offs[Nb*NFRAG*2];
__device__ int   g_jitt[Nb*NFRAG*3];

// ---------------- threefry2x32 (KAT-verified core) ----------------
__device__ __forceinline__ void threefry(unsigned k0, unsigned k1, unsigned &x0, unsigned &x1) {
    unsigned ks0 = k0, ks1 = k1, ks2 = k0 ^ k1 ^ 0x1BD11BDAu;
    x0 += ks0; x1 += ks1;
#define TFRND(r) { x0 += x1; x1 = (x1 << (r)) | (x1 >> (32 - (r))); x1 ^= x0; }
    TFRND(13) TFRND(15) TFRND(26) TFRND(6);  x0 += ks1; x1 += ks2 + 1u;
    TFRND(17) TFRND(29) TFRND(16) TFRND(24); x0 += ks2; x1 += ks0 + 2u;
    TFRND(13) TFRND(15) TFRND(26) TFRND(6);  x0 += ks0; x1 += ks1 + 3u;
    TFRND(17) TFRND(29) TFRND(16) TFRND(24); x0 += ks1; x1 += ks2 + 4u;
    TFRND(13) TFRND(15) TFRND(26) TFRND(6);  x0 += ks2; x1 += ks0 + 5u;
#undef TFRND
}

__device__ __forceinline__ unsigned rb32_part(unsigned k0, unsigned k1, unsigned i) {
    unsigned x0 = 0u, x1 = i;
    threefry(k0, k1, x0, x1);
    return x0 ^ x1;
}

__device__ __forceinline__ void split_key(unsigned k0, unsigned k1, unsigned t,
                                          unsigned &o0, unsigned &o1) {
    unsigned x0 = 0u, x1 = t;
    threefry(k0, k1, x0, x1);
    o0 = x0; o1 = x1;
}

// ---------------- kernel 1: RNG setup + target output ----------------
__global__ void rng_kernel(float* target_out) {
    __shared__ unsigned keys[14];
    __shared__ float noise[Nb*NFRAG];
    int tid = threadIdx.x;

    if (tid == 0) {
        for (int t = 0; t < 3; t++)
            split_key(0u, 42u, (unsigned)t, keys[2*t], keys[2*t+1]);
        split_key(keys[2], keys[3], 0u, keys[6],  keys[7]);
        split_key(keys[2], keys[3], 1u, keys[8],  keys[9]);
        split_key(keys[4], keys[5], 0u, keys[10], keys[11]);
        split_key(keys[4], keys[5], 1u, keys[12], keys[13]);
    }
    __syncthreads();

    if (tid < Nb*NFRAG) {
        unsigned bits = rb32_part(keys[0], keys[1], (unsigned)tid);
        noise[tid] = __uint_as_float((bits >> 9) | 0x3F800000u) - 1.0f;
    }
    __syncthreads();

    if (tid < Nb) {
        int ids[NFRAG];
        unsigned used = 0;
        for (int r = 0; r < NFRAG; r++) {
            int best = -1;
            for (int j = 0; j < NFRAG; j++) {
                if (used & (1u << j)) continue;
                if (best < 0 || noise[tid*NFRAG + j] < noise[tid*NFRAG + best]) best = j;
            }
            ids[r] = best; used |= (1u << best);
        }
        int rest[NFRAG];
        for (int r = 0; r < NFRAG; r++) { g_shuffle[tid*NFRAG + r] = ids[r]; rest[ids[r]] = r; }
        if (target_out) {
            for (int f = 0; f < NFRAG; f++) {
                target_out[(tid*NFRAG + f)*2 + 0] = (float)(rest[f] / 3);
                target_out[(tid*NFRAG + f)*2 + 1] = (float)(rest[f] % 3);
            }
        }
    }

    for (int i = tid; i < Nb*NFRAG*2; i += blockDim.x) {
        unsigned hi = rb32_part(keys[6], keys[7], (unsigned)i);
        unsigned lo = rb32_part(keys[8], keys[9], (unsigned)i);
        unsigned v = (((hi % 12u) * 4u) + (lo % 12u)) % 12u;
        g_offs[i] = (int)v;
    }
    for (int i = tid; i < Nb*NFRAG*3; i += blockDim.x) {
        unsigned hi = rb32_part(keys[10], keys[11], (unsigned)i);
        unsigned lo = rb32_part(keys[12], keys[13], (unsigned)i);
        unsigned v = ((hi % 5u) + (lo % 5u)) % 5u;
        g_jitt[i] = (int)v - 2;
    }
}

// ---------------- block reductions (blockDim == 256) ----------------
__device__ __forceinline__ float bsum256(float v, float* red8) {
    for (int o = 16; o; o >>= 1) v += __shfl_xor_sync(0xFFFFFFFFu, v, o);
    if ((threadIdx.x & 31) == 0) red8[threadIdx.x >> 5] = v;
    __syncthreads();
    float r = red8[0]+red8[1]+red8[2]+red8[3]+red8[4]+red8[5]+red8[6]+red8[7];
    __syncthreads();
    return r;
}

// ---------------- kernel 2: augment ----------------
__global__ void augment_kernel(const float* __restrict__ x) {
    __shared__ float buf[Pfr*Pfr];
    __shared__ float red8[8];
    int bfc = blockIdx.x;
    int c = bfc % 3;
    int bf = bfc / 3;
    int b = bf / NFRAG, f = bf % NFRAG;

    int src = g_shuffle[bf];
    int sr = (src / 3) * Pfr + g_offs[2*bf + 0];
    int sc = (src % 3) * Pfr + g_offs[2*bf + 1];
    float jitv = (float)g_jitt[bf*3 + c];
    const float* xp = x + ((size_t)b*3 + c) * PUZ * PUZ;

    const float sf = 64.0f / 75.0f;
    float lsum = 0.f;
    for (int idx = threadIdx.x; idx < Pfr*Pfr; idx += 256) {
        int i = idx / Pfr, j = idx % Pfr;
        float fy = (i + 0.5f) * sf - 0.5f;
        float fx = (j + 0.5f) * sf - 0.5f;
        int   y0 = (int)floorf(fy); float dy = fy - (float)y0;
        int   x0 = (int)floorf(fx); float dx = fx - (float)x0;
        int y0c = max(0, min(63, y0)),   y1c = max(0, min(63, y0 + 1));
        int x0c = max(0, min(63, x0)),   x1c = max(0, min(63, x0 + 1));
        const float* r0 = xp + (size_t)(sr + y0c) * PUZ + sc;
        const float* r1 = xp + (size_t)(sr + y1c) * PUZ + sc;
        float v = (1.f-dy)*((1.f-dx)*r0[x0c] + dx*r0[x1c])
                +       dy*((1.f-dx)*r1[x0c] + dx*r1[x1c]);
        v = v + jitv;
        v = fminf(fmaxf(v, 0.f), 255.f);
        buf[idx] = v;
        lsum += v;
    }
    float m = bsum256(lsum, red8) * (1.0f / (Pfr*Pfr));
    float lss = 0.f;
    for (int idx = threadIdx.x; idx < Pfr*Pfr; idx += 256) {
        float d = buf[idx] - m;
        lss += d * d;
    }
    float ss = bsum256(lss, red8);
    float s = sqrtf(ss / (float)(Pfr*Pfr - 1));
    if (s == 0.f) s = 1.f;

    int gi = f / 3, gj = f % 3;
    float* op = g_img + ((size_t)b*3 + c) * PUZ * PUZ + (size_t)gi*Pfr*PUZ + gj*Pfr;
    for (int idx = threadIdx.x; idx < Pfr*Pfr; idx += 256) {
        op[(idx / Pfr) * PUZ + (idx % Pfr)] = (buf[idx] - m) / s;
    }
}

// ---------------- kernel 3: patchify ----------------
__global__ void patchify_kernel() {
    int idx = blockIdx.x * blockDim.x + threadIdx.x;
    if (idx >= Nb*NPT*Dm) return;
    int k = idx % Dm;
    int p = (idx / Dm) % NPT;
    int b = idx / (Dm * NPT);
    int c = k >> 8, u = (k >> 4) & 15, v = k & 15;
    int pi = p / 14, pj = p % 14;
    g_patches[idx] = g_img[(((size_t)b*3 + c) * PUZ + (pi*16 + u)) * PUZ + (pj*16 + v)];
}

// ---------------- kernel 4: token assemble ----------------
__global__ void assemble_kernel(const float* __restrict__ clstok, const float* __restrict__ pos) {
    int idx = blockIdx.x * blockDim.x + threadIdx.x;
    if (idx >= Nb*TOKS*Dm) return;
    int d = idx % Dm;
    int t = (idx / Dm) % TOKS;
    int b = idx / (Dm * TOKS);
    float v = (t == 0) ? clstok[d] : g_ptok[((size_t)b*NPT + (t-1))*Dm + d];
    g_tok[idx] = v + pos[t*Dm + d];
}

// ---------------- kernel 5: layernorm ----------------
__global__ void ln_kernel(const float* __restrict__ x, long long sx,
                          const float* __restrict__ s, const float* __restrict__ b,
                          float* __restrict__ y, long long sy) {
    __shared__ float red8[8];
    const float* xr = x + (long long)blockIdx.x * sx;
    float* yr = y + (long long)blockIdx.x * sy;
    int t = threadIdx.x;
    float v0 = xr[t], v1 = xr[t+256], v2 = xr[t+512];
    float m = bsum256(v0+v1+v2, red8) * (1.0f/768.0f);
    float d0 = v0-m, d1 = v1-m, d2 = v2-m;
    float var = bsum256(d0*d0 + d1*d1 + d2*d2, red8) * (1.0f/768.0f);
    float inv = rsqrtf(var + 1e-6f);
    yr[t]     = d0*inv*s[t]     + b[t];
    yr[t+256] = d1*inv*s[t+256] + b[t+256];
    yr[t+512] = d2*inv*s[t+512] + b[t+512];
}

// ---------------- kernel 6a: small fp32 SGEMM (head only) ----------------
template<int ACT>
__global__ void sgemm_kernel(const float* __restrict__ A, const float* __restrict__ B,
                             const float* __restrict__ bias, float* __restrict__ C,
                             int M, int N, int K, int ACCUM) {
    __shared__ float As[16][64];
    __shared__ float Bs[16][64];
    int tid = threadIdx.x;
    int tx = tid & 15, ty = tid >> 4;
    int blockRow = blockIdx.y * 64;
    int blockCol = blockIdx.x * 64;
    float acc[4][4] = {};

    for (int k0 = 0; k0 < K; k0 += 16) {
        #pragma unroll
        for (int t = tid; t < 64*16; t += 256) {
            int m  = t >> 4, kk  = t & 15;
            int gr = blockRow + m, gc = k0 + kk;
            As[kk][m] = (gr < M && gc < K) ? A[(size_t)gr*K + gc] : 0.f;
            int kk2 = t >> 6, nn = t & 63;
            int gr2 = k0 + kk2, gc2 = blockCol + nn;
            Bs[kk2][nn] = (gr2 < K && gc2 < N) ? B[(size_t)gr2*N + gc2] : 0.f;
        }
        __syncthreads();
        #pragma unroll
        for (int kk = 0; kk < 16; kk++) {
            float a[4], bb[4];
            #pragma unroll
            for (int i = 0; i < 4; i++) a[i]  = As[kk][ty*4 + i];
            #pragma unroll
            for (int j = 0; j < 4; j++) bb[j] = Bs[kk][tx*4 + j];
            #pragma unroll
            for (int i = 0; i < 4; i++)
                #pragma unroll
                for (int j = 0; j < 4; j++)
                    acc[i][j] += a[i] * bb[j];
        }
        __syncthreads();
    }

    #pragma unroll
    for (int i = 0; i < 4; i++) {
        int r = blockRow + ty*4 + i;
        if (r >= M) continue;
        #pragma unroll
        for (int j = 0; j < 4; j++) {
            int cc = blockCol + tx*4 + j;
            if (cc >= N) continue;
            float v = acc[i][j] + (bias ? bias[cc] : 0.f);
            if (ACT == 1) v = 0.5f * v * (1.0f + erff(v * 0.70710678118654752f));
            if (ACT == 2) v = fmaxf(v, 0.f);
            size_t oi = (size_t)r * N + cc;
            if (ACCUM) C[oi] += v; else C[oi] = v;
        }
    }
}

// ---------------- kernel 6b: bf16x3 GEMM (m16n8k16), cp.async double-buffered ----------------
// C[M,N] = act(A[M,K] @ B[K,N] + bias) [+= C]; N%128==0, K%32==0, M arbitrary.
#define GBM 128
#define GBN 128
#define GBK 32
#define ASTR 36        // A smem m-major: As[m][k]
#define BSTR 132       // B smem k-major: Bs[k][n]
#define ABUF (GBM*ASTR)
#define BBUF (GBK*BSTR)
#define GEMM_SMEM_BYTES ((2*ABUF + 2*BBUF) * 4)   // 70656 B

// pack two floats to bf16x2: result = {hi16: cvt(vhi), lo16: cvt(vlo)}
__device__ __forceinline__ unsigned packbf(float vhi, float vlo) {
    unsigned r;
    asm("cvt.rn.bf16x2.f32 %0, %1, %2;" : "=r"(r) : "f"(vhi), "f"(vlo));
    return r;
}

// split float pair (v0 lower-k, v1 upper-k) into bf16x2 hi and residual-lo regs
__device__ __forceinline__ void split2(float v0, float v1, unsigned &h, unsigned &l) {
    h = packbf(v1, v0);
    float h0 = __uint_as_float(h << 16);
    float h1 = __uint_as_float(h & 0xFFFF0000u);
    l = packbf(v1 - h1, v0 - h0);
}

__device__ __forceinline__ void mma_bf16(float* c, const unsigned* a, const unsigned* b) {
    asm volatile(
        "mma.sync.aligned.m16n8k16.row.col.f32.bf16.bf16.f32 "
        "{%0,%1,%2,%3}, {%4,%5,%6,%7}, {%8,%9}, {%0,%1,%2,%3};"
        : "+f"(c[0]), "+f"(c[1]), "+f"(c[2]), "+f"(c[3])
        : "r"(a[0]), "r"(a[1]), "r"(a[2]), "r"(a[3]), "r"(b[0]), "r"(b[1]));
}

__device__ __forceinline__ void cp16(unsigned saddr, const void* g, unsigned nbytes) {
    asm volatile("cp.async.ca.shared.global [%0], [%1], 16, %2;\n"
                 :: "r"(saddr), "l"(g), "r"(nbytes));
}

template<int ACT>
__global__ __launch_bounds__(256, 2)
void gemm_tc_kernel(const float* __restrict__ A, const float* __restrict__ B,
                    const float* __restrict__ bias, float* __restrict__ C,
                    int M, int N, int K, int ACCUM) {
    extern __shared__ float gsm[];
    float* As = gsm;              // [2][GBM][ASTR]
    float* Bs = gsm + 2*ABUF;     // [2][GBK][BSTR]
    unsigned asBase = (unsigned)__cvta_generic_to_shared(As);
    unsigned bsBase = (unsigned)__cvta_generic_to_shared(Bs);

    int tid  = threadIdx.x;
    int lane = tid & 31;
    int warp = tid >> 5;
    int g  = lane >> 2;
    int tg = lane & 3;
    int wm = (warp & 3) * 32;
    int wn = (warp >> 2) * 64;

    int rowBase = blockIdx.y * GBM;
    int colBase = blockIdx.x * GBN;

    int am  = tid >> 1;
    int ah4 = (tid & 1) * 16;
    int bk  = tid >> 3;
    int bp  = (tid & 7) * 16;

    const float* gAr = A + (size_t)(rowBase + am) * K + ah4;
    unsigned     aOK = (rowBase + am < M) ? 16u : 0u;
    const float* gBr = B + (size_t)bk * N + colBase + bp;

    float acc[2][8][4];
    #pragma unroll
    for (int mt = 0; mt < 2; mt++)
        #pragma unroll
        for (int nt = 0; nt < 8; nt++)
            #pragma unroll
            for (int i = 0; i < 4; i++) acc[mt][nt][i] = 0.f;

    int nIter = K / GBK;

    {
        unsigned sa = asBase + (unsigned)((am*ASTR + ah4) * 4);
        unsigned sb = bsBase + (unsigned)((bk*BSTR + bp) * 4);
        #pragma unroll
        for (int j = 0; j < 4; j++) cp16(sa + 16*j, gAr + 4*j, aOK);
        #pragma unroll
        for (int j = 0; j < 4; j++) cp16(sb + 16*j, gBr + 4*j, 16u);
        asm volatile("cp.async.commit_group;\n" ::);
    }

    for (int it = 0; it < nIter; it++) {
        int buf = it & 1;
        if (it + 1 < nIter) {
            int nb = (it + 1) & 1;
            int k0n = (it + 1) * GBK;
            unsigned sa = asBase + (unsigned)((nb*ABUF + am*ASTR + ah4) * 4);
            unsigned sb = bsBase + (unsigned)((nb*BBUF + bk*BSTR + bp) * 4);
            const float* ga = gAr + k0n;
            const float* gb = gBr + (size_t)k0n * N;
            #pragma unroll
            for (int j = 0; j < 4; j++) cp16(sa + 16*j, ga + 4*j, aOK);
            #pragma unroll
            for (int j = 0; j < 4; j++) cp16(sb + 16*j, gb + 4*j, 16u);
            asm volatile("cp.async.commit_group;\n" ::);
            asm volatile("cp.async.wait_group 1;\n" ::);
        } else {
            asm volatile("cp.async.wait_group 0;\n" ::);
        }
        __syncthreads();

        const float* Ab = As + buf*ABUF;
        const float* Bb = Bs + buf*BBUF;

        #pragma unroll
        for (int kk = 0; kk < GBK; kk += 16) {
            unsigned ah[2][4], al[2][4], bh[8][2], bl[8][2];
            // A fragments: reg r -> row (g + (r&1)*8), k (kk + 2tg + (r>>1)*8), float2 pair
            #pragma unroll
            for (int mt = 0; mt < 2; mt++) {
                int mb = wm + mt * 16;
                #pragma unroll
                for (int r = 0; r < 4; r++) {
                    int row = mb + g + (r & 1) * 8;
                    int kc  = kk + 2*tg + (r >> 1) * 8;
                    float2 v = *reinterpret_cast<const float2*>(&Ab[row*ASTR + kc]);
                    split2(v.x, v.y, ah[mt][r], al[mt][r]);
                }
            }
            // B fragments: b0 -> k=kk+2tg,kk+2tg+1 col n; b1 -> +8
            #pragma unroll
            for (int nt = 0; nt < 8; nt++) {
                int n = wn + nt * 8 + g;
                float v0 = Bb[(kk + 2*tg)     * BSTR + n];
                float v1 = Bb[(kk + 2*tg + 1) * BSTR + n];
                float w0 = Bb[(kk + 2*tg + 8) * BSTR + n];
                float w1 = Bb[(kk + 2*tg + 9) * BSTR + n];
                split2(v0, v1, bh[nt][0], bl[nt][0]);
                split2(w0, w1, bh[nt][1], bl[nt][1]);
            }
            #pragma unroll
            for (int mt = 0; mt < 2; mt++)
                #pragma unroll
                for (int nt = 0; nt < 8; nt++) {
                    mma_bf16(acc[mt][nt], ah[mt], bh[nt]);   // hi*hi
                    mma_bf16(acc[mt][nt], ah[mt], bl[nt]);   // hi*lo
                    mma_bf16(acc[mt][nt], al[mt], bh[nt]);   // lo*hi
                }
        }
        __syncthreads();
    }

    #pragma unroll
    for (int mt = 0; mt < 2; mt++) {
        int r1 = rowBase + wm + mt * 16 + g;
        int r2 = r1 + 8;
        #pragma unroll
        for (int nt = 0; nt < 8; nt++) {
            int col = colBase + wn + nt * 8 + tg * 2;
            float bv0 = bias ? bias[col]     : 0.f;
            float bv1 = bias ? bias[col + 1] : 0.f;
            #pragma unroll
            for (int half = 0; half < 2; half++) {
                int r = half ? r2 : r1;
                if (r >= M) continue;
                float v0 = acc[mt][nt][half*2 + 0] + bv0;
                float v1 = acc[mt][nt][half*2 + 1] + bv1;
                if (ACT == 1) {
                    v0 = 0.5f * v0 * (1.0f + erff(v0 * 0.70710678118654752f));
                    v1 = 0.5f * v1 * (1.0f + erff(v1 * 0.70710678118654752f));
                }
                if (ACT == 2) { v0 = fmaxf(v0, 0.f); v1 = fmaxf(v1, 0.f); }
                size_t oi = (size_t)r * N + col;
                if (ACCUM) { C[oi] += v0; C[oi + 1] += v1; }
                else       { C[oi]  = v0; C[oi + 1]  = v1; }
            }
        }
    }
}

// ---------------- kernel 7: attention (K transposed in smem, conflict-free) ----------------
#define QT 8
#define SCP 208
#define TOKSP 201
#define ATTN_SMEM_FLOATS (HD*TOKSP + TOKS*HD + QT*HD + QT*SCP + 16)
__global__ void attn_kernel() {
    extern __shared__ float sm[];
    float* Kt = sm;
    float* Vs = Kt + HD*TOKSP;
    float* Qs = Vs + TOKS*HD;
    float* Sc = Qs + QT*HD;
    float* rowinv = Sc + QT*SCP;

    int bh = blockIdx.x;
    int b = bh / NHEAD, h = bh % NHEAD;
    int tid = threadIdx.x;
    const float* base = g_qkv + (size_t)b * TOKS * (3*Dm) + h * HD;

    for (int i = tid; i < TOKS*HD; i += 256) {
        int t = i >> 6, d = i & 63;
        Kt[d*TOKSP + t] = base[(size_t)t*(3*Dm) + Dm   + d];
        Vs[i]           = base[(size_t)t*(3*Dm) + 2*Dm + d];
    }
    __syncthreads();

    for (int q0 = 0; q0 < TOKS; q0 += QT) {
        int qn = min(QT, TOKS - q0);
        for (int i = tid; i < qn*HD; i += 256) {
            int qi = i >> 6, d = i & 63;
            Qs[qi*HD + d] = base[(size_t)(q0 + qi)*(3*Dm) + d];
        }
        __syncthreads();
        for (int qi = 0; qi < qn; qi++) {
            const float* qr = Qs + qi*HD;
            for (int j = tid; j < TOKS; j += 256) {
                float s = 0.f;
                #pragma unroll
                for (int d = 0; d < HD; d++) s += qr[d] * Kt[d*TOKSP + j];
                Sc[qi*SCP + j] = s * 0.125f;
            }
        }
        __syncthreads();
        {
            int w = tid >> 5, lane = tid & 31;
            if (w < qn) {
                float* row = Sc + w*SCP;
                float lm = -1e30f;
                for (int j = lane; j < TOKS; j += 32) lm = fmaxf(lm, row[j]);
                for (int o = 16; o; o >>= 1) lm = fmaxf(lm, __shfl_xor_sync(0xFFFFFFFFu, lm, o));
                float ls = 0.f;
                for (int j = lane; j < TOKS; j += 32) { float e = expf(row[j] - lm); row[j] = e; ls += e; }
                for (int o = 16; o; o >>= 1) ls += __shfl_xor_sync(0xFFFFFFFFu, ls, o);
                if (lane == 0) rowinv[w] = 1.f / ls;
            }
        }
        __syncthreads();
        for (int idx = tid; idx < qn*HD; idx += 256) {
            int qi = idx >> 6, d = idx & 63;
            const float* row = Sc + qi*SCP;
            float acc = 0.f;
            #pragma unroll 4
            for (int j = 0; j < TOKS; j++) acc += row[j] * Vs[j*HD + d];
            g_atto[((size_t)b*TOKS + q0 + qi)*Dm + h*HD + d] = acc * rowinv[qi];
        }
        __syncthreads();
    }
}

// ---------------- host ----------------
extern "C" void kernel_launch(void* const* d_in, const int* in_sizes, int n_in,
                              void* d_out, int out_size) {
    const float* x        = (const float*)d_in[0];
    const float* patch_w  = (const float*)d_in[1];
    const float* patch_b  = (const float*)d_in[2];
    const float* cls_tok  = (const float*)d_in[3];
    const float* pos_emb  = (const float*)d_in[4];
    const float* ln1_s    = (const float*)d_in[5];
    const float* ln1_b    = (const float*)d_in[6];
    const float* qkv_w    = (const float*)d_in[7];
    const float* qkv_b    = (const float*)d_in[8];
    const float* proj_w   = (const float*)d_in[9];
    const float* proj_b   = (const float*)d_in[10];
    const float* ln2_s    = (const float*)d_in[11];
    const float* ln2_b    = (const float*)d_in[12];
    const float* mlp1_w   = (const float*)d_in[13];
    const float* mlp1_b   = (const float*)d_in[14];
    const float* mlp2_w   = (const float*)d_in[15];
    const float* mlp2_b   = (const float*)d_in[16];
    const float* lnf_s    = (const float*)d_in[17];
    const float* lnf_b    = (const float*)d_in[18];
    const float* head_w   = (const float*)d_in[19];
    const float* head_b   = (const float*)d_in[20];
    const float* fc1_w    = (const float*)d_in[21];
    const float* fc1_b    = (const float*)d_in[22];
    const float* fc2_w    = (const float*)d_in[23];
    const float* fc2_b    = (const float*)d_in[24];
    float* out = (float*)d_out;

    float *p_patches, *p_ptok, *p_tok, *p_h, *p_mlp, *p_atto, *p_cls, *p_feat, *p_fc1, *p_qkv;
    cudaGetSymbolAddress((void**)&p_patches, g_patches);
    cudaGetSymbolAddress((void**)&p_ptok,    g_ptok);
    cudaGetSymbolAddress((void**)&p_tok,     g_tok);
    cudaGetSymbolAddress((void**)&p_h,       g_h);
    cudaGetSymbolAddress((void**)&p_mlp,     g_mlp);
    cudaGetSymbolAddress((void**)&p_atto,    g_atto);
    cudaGetSymbolAddress((void**)&p_cls,     g_cls);
    cudaGetSymbolAddress((void**)&p_feat,    g_feat);
    cudaGetSymbolAddress((void**)&p_fc1,     g_fc1);
    cudaGetSymbolAddress((void**)&p_qkv,     g_qkv);

    const int ATTN_SMEM = ATTN_SMEM_FLOATS * (int)sizeof(float);
    cudaFuncSetAttribute(attn_kernel, cudaFuncAttributeMaxDynamicSharedMemorySize, ATTN_SMEM);
    cudaFuncSetAttribute(gemm_tc_kernel<0>, cudaFuncAttributeMaxDynamicSharedMemorySize, GEMM_SMEM_BYTES);
    cudaFuncSetAttribute(gemm_tc_kernel<1>, cudaFuncAttributeMaxDynamicSharedMemorySize, GEMM_SMEM_BYTES);

    float* target_out = (out_size >= Nb*NFRAG*2*2) ? (out + Nb*NFRAG*2) : nullptr;
    rng_kernel<<<1, 512>>>(target_out);

    augment_kernel<<<Nb*NFRAG*3, 256>>>(x);

    {
        int total = Nb*NPT*Dm;
        patchify_kernel<<<(total + 255)/256, 256>>>();
    }

    auto g64  = [](int M, int N) { return dim3((unsigned)((N + 63)/64),  (unsigned)((M + 63)/64)); };
    auto g128 = [](int M, int N) { return dim3((unsigned)(N/128), (unsigned)((M + 127)/128)); };

    gemm_tc_kernel<0><<<g128(Nb*NPT, Dm), 256, GEMM_SMEM_BYTES>>>(p_patches, patch_w, patch_b, p_ptok, Nb*NPT, Dm, Dm, 0);
    {
        int total = Nb*TOKS*Dm;
        assemble_kernel<<<(total + 255)/256, 256>>>(cls_tok, pos_emb);
    }

    for (int l = 0; l < NL; l++) {
        ln_kernel<<<ROWS, 256>>>(p_tok, Dm, ln1_s + (size_t)l*Dm, ln1_b + (size_t)l*Dm, p_h, Dm);
        gemm_tc_kernel<0><<<g128(ROWS, 3*Dm), 256, GEMM_SMEM_BYTES>>>(p_h, qkv_w + (size_t)l*Dm*3*Dm, qkv_b + (size_t)l*3*Dm,
                                                       p_qkv, ROWS, 3*Dm, Dm, 0);
        attn_kernel<<<Nb*NHEAD, 256, ATTN_SMEM>>>();
        gemm_tc_kernel<0><<<g128(ROWS, Dm), 256, GEMM_SMEM_BYTES>>>(p_atto, proj_w + (size_t)l*Dm*Dm, proj_b + (size_t)l*Dm,
                                                     p_tok, ROWS, Dm, Dm, 1);
        ln_kernel<<<ROWS, 256>>>(p_tok, Dm, ln2_s + (size_t)l*Dm, ln2_b + (size_t)l*Dm, p_h, Dm);
        gemm_tc_kernel<1><<<g128(ROWS, MLPD), 256, GEMM_SMEM_BYTES>>>(p_h, mlp1_w + (size_t)l*Dm*MLPD, mlp1_b + (size_t)l*MLPD,
                                                       p_mlp, ROWS, MLPD, Dm, 0);
        gemm_tc_kernel<0><<<g128(ROWS, Dm), 256, GEMM_SMEM_BYTES>>>(p_mlp, mlp2_w + (size_t)l*MLPD*Dm, mlp2_b + (size_t)l*Dm,
                                                     p_tok, ROWS, Dm, MLPD, 1);
    }

    ln_kernel<<<Nb, 256>>>(p_tok, (long long)TOKS*Dm, lnf_s, lnf_b, p_cls, Dm);
    sgemm_kernel<0><<<g64(Nb, NCLS), 256>>>(p_cls, head_w, head_b, p_feat, Nb, NCLS, Dm, 0);
    sgemm_kernel<2><<<g64(Nb, NCLS), 256>>>(p_feat, fc1_w, fc1_b, p_fc1, Nb, NCLS, NCLS, 0);
    sgemm_kernel<0><<<g64(Nb, NFRAG*2), 256>>>(p_fc1, fc2_w, fc2_b, out, Nb, NFRAG*2, NCLS, 0);
}